// round 13
// baseline (speedup 1.0000x reference)
#include <cuda_runtime.h>
#include <cuda_bf16.h>
#include <cstdint>
#include <math.h>

#define H 128
#define AP 136           // fp32 scratch stride; 136 % 32 == 8 -> conflict-free LDS.64
#define NODES 32         // nodes per CTA
#define GPC 4            // graphs per CTA
#define NT 256           // 8 warps: warp = (mt = w&1, colblock = w>>1)
#define PXS 36           // packed row stride in uint4 (144 words = 16 mod 32 -> conflict-free)

// shared layout (float offsets): three packed buffers + overlays
#define OFF_PA  0                        // packed A / s / h ; also ho (fp32) after gemm6
#define OFF_PB  (OFF_PA + NODES*PXS*4)   // 4608: pre1 fp32 scratch / packed B / upd / x
#define OFF_PX  (OFF_PB + NODES*PXS*4)   // 9216: packed X0 ; also sG (fp32) after gemm5
#define OFF_POS (OFF_PX + NODES*PXS*4)   // 13824
#define OFF_D   (OFF_POS + NODES*2)      // 13888
#define OFF_INT (OFF_D + NODES*8)        // 14144
#define SMEM_FLOATS (OFF_INT + 80)       // 14224 floats = 56896 B -> 3 CTAs/SM (L1D ~57KB)

// packed weights: 7 matrices x [kc(8)][c(128)][t(4)] entries of uint4 {bh01, bh89, bl01, bl89}
#define NMAT 7
#define MAT_ENTRIES (8 * 128 * 4)
__device__ uint4 g_Wpk[NMAT * MAT_ENTRIES];   // 448 KB

// ---- bf16 helpers ----
__device__ __forceinline__ uint32_t bpack(float lo, float hi) {   // lo -> bits[0:16), hi -> bits[16:32)
    uint32_t r;
    asm("cvt.rn.bf16x2.f32 %0, %1, %2;" : "=r"(r) : "f"(hi), "f"(lo));
    return r;
}
__device__ __forceinline__ float bf_lo(uint32_t p) { return __uint_as_float(p << 16); }
__device__ __forceinline__ float bf_hi(uint32_t p) { return __uint_as_float(p & 0xffff0000u); }

__device__ __forceinline__ void bsplit2(float2 v, uint32_t& h, uint32_t& l) {
    h = bpack(v.x, v.y);
    l = bpack(v.x - bf_lo(h), v.y - bf_hi(h));
}
__device__ __forceinline__ uint4 pack_entry(float v0, float v1, float v8, float v9) {
    uint32_t h01 = bpack(v0, v1);
    uint32_t l01 = bpack(v0 - bf_lo(h01), v1 - bf_hi(h01));
    uint32_t h89 = bpack(v8, v9);
    uint32_t l89 = bpack(v8 - bf_lo(h89), v9 - bf_hi(h89));
    return make_uint4(h01, h89, l01, l89);
}
__device__ __forceinline__ float4 unpack_entry(uint4 e) {
    return make_float4(bf_lo(e.x) + bf_lo(e.z), bf_hi(e.x) + bf_hi(e.z),
                       bf_lo(e.y) + bf_lo(e.w), bf_hi(e.y) + bf_hi(e.w));
}

// ---- prep kernel: pack weight matrices into mma-B-fragment order, pre-split bf16 hi/lo ----
__global__ void prep_weights_kernel(const float* __restrict__ pre_W2,
                                    const float* __restrict__ msg_W1,
                                    const float* __restrict__ msg_W2,
                                    const float* __restrict__ post_W1,
                                    const float* __restrict__ post_W2)
{
    int idx = blockIdx.x * blockDim.x + threadIdx.x;
    if (idx >= NMAT * MAT_ENTRIES) return;
    int t  = idx & 3;
    int c  = (idx >> 2) & 127;
    int kc = (idx >> 9) & 7;
    int m  = idx >> 12;

    const float* W;
    switch (m) {
        case 0: W = pre_W2; break;
        case 1: W = msg_W1; break;
        case 2: W = msg_W1 + H * H; break;
        case 3: W = msg_W2; break;
        case 4: W = post_W1; break;
        case 5: W = post_W1 + H * H; break;
        default: W = post_W2; break;
    }
    int k0 = kc * 16 + 2 * t;
    float w0 = W[(k0    ) * H + c];
    float w1 = W[(k0 + 1) * H + c];
    float w8 = W[(k0 + 8) * H + c];
    float w9 = W[(k0 + 9) * H + c];
    g_Wpk[idx] = pack_entry(w0, w1, w8, w9);
}

__device__ __forceinline__ void mma_bf16(float* c, const uint32_t* a, const uint32_t* b)
{
    asm volatile(
        "mma.sync.aligned.m16n8k16.row.col.f32.bf16.bf16.f32 "
        "{%0,%1,%2,%3}, {%4,%5,%6,%7}, {%8,%9}, {%0,%1,%2,%3};"
        : "+f"(c[0]), "+f"(c[1]), "+f"(c[2]), "+f"(c[3])
        : "r"(a[0]), "r"(a[1]), "r"(a[2]), "r"(a[3]), "r"(b[0]), "r"(b[1]));
}

// fp32-A variant (gemm0 only). Warp covers rows mt*16..+15, cols cb*32..+31.
__device__ __forceinline__ void gemm_acc(const float* __restrict__ X,
                                         int mat, float acc[4][4])
{
    const uint4* __restrict__ Wp = g_Wpk + mat * MAT_ENTRIES;
    const int lane = threadIdx.x & 31;
    const int warp = threadIdx.x >> 5;
    const int mt = warp & 1;
    const int n0 = (warp >> 1) * 32;
    const int g = lane >> 2, tig = lane & 3;
    const int r = mt * 16 + g;

#pragma unroll
    for (int kc = 0; kc < 8; ++kc) {
        const int kk = kc * 16;
        uint4 bfr[4];
#pragma unroll
        for (int nt = 0; nt < 4; ++nt)
            bfr[nt] = __ldg(&Wp[((kc << 7) + n0 + nt * 8 + g) * 4 + tig]);

        uint32_t ah[4], al[4];
        float2 a01 = *(const float2*)&X[ r      * AP + kk + 2 * tig];
        float2 c01 = *(const float2*)&X[(r + 8) * AP + kk + 2 * tig];
        float2 a89 = *(const float2*)&X[ r      * AP + kk + 2 * tig + 8];
        float2 c89 = *(const float2*)&X[(r + 8) * AP + kk + 2 * tig + 8];
        bsplit2(a01, ah[0], al[0]);
        bsplit2(c01, ah[1], al[1]);
        bsplit2(a89, ah[2], al[2]);
        bsplit2(c89, ah[3], al[3]);
#pragma unroll
        for (int nt = 0; nt < 4; ++nt) {
            uint32_t bh[2] = {bfr[nt].x, bfr[nt].y};
            uint32_t bl[2] = {bfr[nt].z, bfr[nt].w};
            mma_bf16(acc[nt], ah, bh);
            mma_bf16(acc[nt], al, bh);
            mma_bf16(acc[nt], ah, bl);
        }
    }
}

// packed-A variant: X pre-split in fragment order (uint4 {h01,h89,l01,l89}, stride PXS)
__device__ __forceinline__ void gemm_acc_pk(const uint4* __restrict__ PX,
                                            int mat, float acc[4][4])
{
    const uint4* __restrict__ Wp = g_Wpk + mat * MAT_ENTRIES;
    const int lane = threadIdx.x & 31;
    const int warp = threadIdx.x >> 5;
    const int mt = warp & 1;
    const int n0 = (warp >> 1) * 32;
    const int g = lane >> 2, tig = lane & 3;
    const int r = mt * 16 + g;

#pragma unroll
    for (int kc = 0; kc < 8; ++kc) {
        uint4 bfr[4];
#pragma unroll
        for (int nt = 0; nt < 4; ++nt)
            bfr[nt] = __ldg(&Wp[((kc << 7) + n0 + nt * 8 + g) * 4 + tig]);

        uint4 e0 = PX[ r      * PXS + kc * 4 + tig];
        uint4 e1 = PX[(r + 8) * PXS + kc * 4 + tig];
        uint32_t ah[4] = {e0.x, e1.x, e0.y, e1.y};
        uint32_t al[4] = {e0.z, e1.z, e0.w, e1.w};

#pragma unroll
        for (int nt = 0; nt < 4; ++nt) {
            uint32_t bh[2] = {bfr[nt].x, bfr[nt].y};
            uint32_t bl[2] = {bfr[nt].z, bfr[nt].w};
            mma_bf16(acc[nt], ah, bh);
            mma_bf16(acc[nt], al, bh);
            mma_bf16(acc[nt], ah, bl);
        }
    }
}

// packed epilogue: store pre-split bf16 hi/lo fragments
__device__ __forceinline__ void gemm_epi_pk(float acc[4][4], uint4* __restrict__ PX,
                                            const float* __restrict__ gbias, float biasScale,
                                            bool doRelu)
{
    const int lane = threadIdx.x & 31;
    const int warp = threadIdx.x >> 5;
    const int mt = warp & 1;
    const int cb = warp >> 1;
    const int n0 = cb * 32;
    const int g = lane >> 2, tig = lane & 3;

    float2 bz[4];
#pragma unroll
    for (int nt = 0; nt < 4; ++nt) {
        bz[nt] = make_float2(0.f, 0.f);
        if (gbias) {
            float2 b = *(const float2*)&gbias[n0 + nt * 8 + 2 * tig];
            bz[nt].x = biasScale * b.x; bz[nt].y = biasScale * b.y;
        }
    }
#pragma unroll
    for (int h = 0; h < 2; ++h) {
        int rr = mt * 16 + h * 8 + g;
#pragma unroll
        for (int cc = 0; cc < 2; ++cc) {
            int ntA = 2 * cc, ntB = 2 * cc + 1;
            float v0x = acc[ntA][h * 2 + 0] + bz[ntA].x;
            float v0y = acc[ntA][h * 2 + 1] + bz[ntA].y;
            float v1x = acc[ntB][h * 2 + 0] + bz[ntB].x;
            float v1y = acc[ntB][h * 2 + 1] + bz[ntB].y;
            if (doRelu) {
                v0x = fmaxf(v0x, 0.f); v0y = fmaxf(v0y, 0.f);
                v1x = fmaxf(v1x, 0.f); v1y = fmaxf(v1y, 0.f);
            }
            PX[rr * PXS + (2 * cb + cc) * 4 + tig] = pack_entry(v0x, v0y, v1x, v1y);
        }
    }
}

#define ACC_ZERO(acc) do {                                             \
    _Pragma("unroll")                                                  \
    for (int _n = 0; _n < 4; ++_n)                                     \
        _Pragma("unroll")                                              \
        for (int _i = 0; _i < 4; ++_i) acc[_n][_i] = 0.f;              \
} while (0)

__global__ __launch_bounds__(NT, 3) void prettyrnn_kernel(
    const int* __restrict__ anchors, const int* __restrict__ n_jumps,
    const float* __restrict__ positions, const int* __restrict__ colors,
    const int* __restrict__ markers,
    const float* __restrict__ pre_W1, const float* __restrict__ pre_b1,
    const float* __restrict__ pre_b2,
    const float* __restrict__ msg_W1, const float* __restrict__ msg_b1,
    const float* __restrict__ msg_b2,
    const float* __restrict__ post_b1, const float* __restrict__ post_b2,
    const float* __restrict__ out_W1, const float* __restrict__ out_b1,
    const float* __restrict__ out_W2, const float* __restrict__ out_b2,
    float* __restrict__ out)
{
    extern __shared__ float sm[];
    uint4* sPA = (uint4*)(sm + OFF_PA);
    uint4* sPB = (uint4*)(sm + OFF_PB);
    uint4* sPX = (uint4*)(sm + OFF_PX);
    float* sPre = sm + OFF_PB;            // fp32 scratch for pre-layer-1 output (stride AP)
    float* sG   = sm + OFF_PX;            // fp32 graph sums (overlaid; PX dead by then)
    float* sHO  = sm + OFF_PA;            // fp32 out-layer-1 output (overlaid; PA dead)
    float* sPos = sm + OFF_POS;
    float* sD   = sm + OFF_D;
    int* sCol = (int*)(sm + OFF_INT);
    int* sMrk = sCol + NODES;
    int* sAnc = sMrk + NODES;
    int* sJmp = sAnc + GPC;

    const int tid = threadIdx.x;
    const int lane = tid & 31;
    const int warp = tid >> 5;
    const int nodeBase = blockIdx.x * NODES;
    const int graphBase = blockIdx.x * GPC;
    // entry-column decode for (lane = entry) stages
    const int ew = lane >> 3, ecc = (lane >> 2) & 1, et = lane & 3;
    const int cA = 32 * ew + 16 * ecc + 2 * et;
    const int cB = cA + 8;

    // ---- phase 0: per-node / per-graph inputs ----
    if (tid < NODES) {
        sCol[tid] = colors[nodeBase + tid];
        sMrk[tid] = markers[nodeBase + tid];
        sPos[2 * tid]     = positions[2 * (nodeBase + tid)];
        sPos[2 * tid + 1] = positions[2 * (nodeBase + tid) + 1];
    }
    if (tid >= NODES && tid < NODES + GPC) {
        int g = tid - NODES;
        sAnc[g] = anchors[graphBase + g];
        sJmp[g] = n_jumps[graphBase + g];
    }
    __syncthreads();

    // ---- distances (NODES*8 = 256 = NT: one per thread) ----
    {
        int idx = tid;
        int n = idx >> 3, jj = idx & 7;
        int j = (n & ~7) + jj;
        float dx = sPos[2 * n]     - sPos[2 * j];
        float dy = sPos[2 * n + 1] - sPos[2 * j + 1];
        sD[idx] = sqrtf(dx * dx + dy * dy);
    }

    // ---- pre layer 1 (coalesced gather): warp w -> rows 4w..4w+3, lane -> 4 consecutive cols ----
    {
        const float4* b1v = (const float4*)pre_b1;
#pragma unroll
        for (int r = 0; r < 4; ++r) {
            int n = warp * 4 + r;
            int g = n >> 3;
            float px = sPos[2 * n], py = sPos[2 * n + 1];
            const float4* rw0 = (const float4*)(pre_W1);
            const float4* rw1 = (const float4*)(pre_W1 + H);
            const float4* rc  = (const float4*)(pre_W1 + (2 + sCol[n]) * H);
            const float4* rm  = (const float4*)(pre_W1 + (10 + (sMrk[n] - 8)) * H);
            const float4* ra  = (const float4*)(pre_W1 + (18 + sAnc[g]) * H);
            const float4* rj  = (const float4*)(pre_W1 + (34 + sJmp[g]) * H);

            float4 vc = __ldg(&rc[lane]);
            float4 vm = __ldg(&rm[lane]);
            float4 va = __ldg(&ra[lane]);
            float4 vj = __ldg(&rj[lane]);
            float4 vb = __ldg(&b1v[lane]);
            float4 v0 = __ldg(&rw0[lane]);
            float4 v1 = __ldg(&rw1[lane]);

            float4 o;
            o.x = fmaxf(fmaf(px, v0.x, fmaf(py, v1.x, vc.x + vm.x + va.x + vj.x + vb.x)), 0.f);
            o.y = fmaxf(fmaf(px, v0.y, fmaf(py, v1.y, vc.y + vm.y + va.y + vj.y + vb.y)), 0.f);
            o.z = fmaxf(fmaf(px, v0.z, fmaf(py, v1.z, vc.z + vm.z + va.z + vj.z + vb.z)), 0.f);
            o.w = fmaxf(fmaf(px, v0.w, fmaf(py, v1.w, vc.w + vm.w + va.w + vj.w + vb.w)), 0.f);
            *(float4*)&sPre[n * AP + 4 * lane] = o;
        }
    }
    __syncthreads();

    // ---- pre layer 2 (linear): x0 = h1 @ pre_W2 + b2 -> sPX (packed) ----
    {
        float acc[4][4]; ACC_ZERO(acc);
        gemm_acc(sPre, 0, acc);
        gemm_epi_pk(acc, sPX, pre_b2, 1.f, false);
    }
    __syncthreads();

    // ---- A = x0 @ msg_W1[0:128] -> sPA ; B = x0 @ msg_W1[128:256] -> sPB (both packed) ----
    {
        float acc[4][4]; ACC_ZERO(acc);
        gemm_acc_pk(sPX, 1, acc);
        gemm_epi_pk(acc, sPA, nullptr, 0.f, false);
    }
    {
        float acc[4][4]; ACC_ZERO(acc);
        gemm_acc_pk(sPX, 2, acc);
        gemm_epi_pk(acc, sPB, nullptr, 0.f, false);
    }
    __syncthreads();

    // ---- edge aggregation on packed entries: warp -> (octet = w>>1, rows half*4..+3), lane = entry ----
    //      s[n] = sum_{j!=n} relu(A[n]+B[j]+d*w1d+b1)  -> sPA (packed, in place)
    {
        const float* w1d = msg_W1 + 2 * H * H;
        float2 wvA = __ldg((const float2*)&w1d[cA]);
        float2 wvB = __ldg((const float2*)&w1d[cB]);
        float2 bvA = __ldg((const float2*)&msg_b1[cA]);
        float2 bvB = __ldg((const float2*)&msg_b1[cB]);
        const int octet = warp >> 1;
        const int half = warp & 1;
        const int base = octet * 8;
        const int rbase = half * 4;

        float4 a[4], s[4];
#pragma unroll
        for (int i = 0; i < 4; ++i) {
            a[i] = unpack_entry(sPA[(base + rbase + i) * PXS + lane]);
            s[i] = make_float4(0.f, 0.f, 0.f, 0.f);
        }
#pragma unroll
        for (int j = 0; j < 8; ++j) {
            float4 B = unpack_entry(sPB[(base + j) * PXS + lane]);
#pragma unroll
            for (int i = 0; i < 4; ++i) {
                int nloc = rbase + i;
                float d = sD[(base + nloc) * 8 + j];
                float tx = fmaxf(a[i].x + B.x + fmaf(d, wvA.x, bvA.x), 0.f);
                float ty = fmaxf(a[i].y + B.y + fmaf(d, wvA.y, bvA.y), 0.f);
                float tz = fmaxf(a[i].z + B.z + fmaf(d, wvB.x, bvB.x), 0.f);
                float tw = fmaxf(a[i].w + B.w + fmaf(d, wvB.y, bvB.y), 0.f);
                if (j != nloc) {
                    s[i].x += tx; s[i].y += ty; s[i].z += tz; s[i].w += tw;
                }
            }
        }
#pragma unroll
        for (int i = 0; i < 4; ++i)
            sPA[(base + rbase + i) * PXS + lane] = pack_entry(s[i].x, s[i].y, s[i].z, s[i].w);
    }
    __syncthreads();

    // ---- upd = s @ msg_W2 + 7*msg_b2 -> sPB (packed) ----
    {
        float acc[4][4]; ACC_ZERO(acc);
        gemm_acc_pk(sPA, 3, acc);
        gemm_epi_pk(acc, sPB, msg_b2, 7.f, false);
    }
    __syncthreads();

    // ---- post layer 1 (fused 2K): h = relu(upd@P1a + x0@P1b + b1) -> sPA (packed) ----
    {
        float acc[4][4]; ACC_ZERO(acc);
        gemm_acc_pk(sPB, 4, acc);
        gemm_acc_pk(sPX, 5, acc);
        gemm_epi_pk(acc, sPA, post_b1, 1.f, true);
    }
    __syncthreads();

    // ---- post layer 2: x = h @ post_W2 + b2 -> sPB (packed) ----
    {
        float acc[4][4]; ACC_ZERO(acc);
        gemm_acc_pk(sPA, 6, acc);
        gemm_epi_pk(acc, sPB, post_b2, 1.f, false);
    }
    __syncthreads();

    // ---- graph sum (packed -> fp32 sG in PX region): warps 0..3, warp = graph, lane = entry ----
    if (warp < GPC) {
        float4 s = make_float4(0.f, 0.f, 0.f, 0.f);
#pragma unroll
        for (int i = 0; i < 8; ++i) {
            float4 v = unpack_entry(sPB[(warp * 8 + i) * PXS + lane]);
            s.x += v.x; s.y += v.y; s.z += v.z; s.w += v.w;
        }
        *(float2*)&sG[warp * AP + cA] = make_float2(s.x, s.y);
        *(float2*)&sG[warp * AP + cB] = make_float2(s.z, s.w);
    }
    __syncthreads();

    // ---- out layer 1 (SIMT): thread-half -> 2 graphs, col = tid&127 ----
    {
        int col = tid & 127;
        int g0 = (tid >> 7) * 2;
        float s0 = __ldg(&out_b1[col]);
        float s1 = s0;
#pragma unroll 4
        for (int kk = 0; kk < H; ++kk) {
            float w = __ldg(&out_W1[kk * H + col]);
            s0 = fmaf(sG[(g0    ) * AP + kk], w, s0);
            s1 = fmaf(sG[(g0 + 1) * AP + kk], w, s1);
        }
        sHO[(g0    ) * AP + col] = fmaxf(s0, 0.f);
        sHO[(g0 + 1) * AP + col] = fmaxf(s1, 0.f);
    }
    __syncthreads();

    // ---- out layer 2 (SIMT): logits -> gmem ----
    if (tid < GPC * 16) {
        int g = tid >> 4, o = tid & 15;
        float s = __ldg(&out_b2[o]);
#pragma unroll 8
        for (int k = 0; k < H; ++k)
            s = fmaf(sHO[g * AP + k], __ldg(&out_W2[k * 16 + o]), s);
        out[(graphBase + g) * 16 + o] = s;
    }
}

extern "C" void kernel_launch(void* const* d_in, const int* in_sizes, int n_in,
                              void* d_out, int out_size)
{
    const int*   anchors   = (const int*)d_in[0];
    const int*   n_jumps   = (const int*)d_in[1];
    const float* positions = (const float*)d_in[2];
    const int*   colors    = (const int*)d_in[3];
    const int*   markers   = (const int*)d_in[4];
    const float* pre_W1  = (const float*)d_in[5];
    const float* pre_b1  = (const float*)d_in[6];
    const float* pre_W2  = (const float*)d_in[7];
    const float* pre_b2  = (const float*)d_in[8];
    const float* msg_W1  = (const float*)d_in[9];
    const float* msg_b1  = (const float*)d_in[10];
    const float* msg_W2  = (const float*)d_in[11];
    const float* msg_b2  = (const float*)d_in[12];
    const float* post_W1 = (const float*)d_in[13];
    const float* post_b1 = (const float*)d_in[14];
    const float* post_W2 = (const float*)d_in[15];
    const float* post_b2 = (const float*)d_in[16];
    const float* out_W1  = (const float*)d_in[17];
    const float* out_b1  = (const float*)d_in[18];
    const float* out_W2  = (const float*)d_in[19];
    const float* out_b2  = (const float*)d_in[20];

    // 1) pack + pre-split weights (same every call: deterministic, graph-capturable)
    int prepThreads = NMAT * MAT_ENTRIES;
    prep_weights_kernel<<<(prepThreads + 255) / 256, 256>>>(
        pre_W2, msg_W1, msg_W2, post_W1, post_W2);

    // 2) main fused kernel
    int bs = in_sizes[0];
    int blocks = bs / GPC;
    size_t smemBytes = SMEM_FLOATS * sizeof(float);
    cudaFuncSetAttribute(prettyrnn_kernel,
                         cudaFuncAttributeMaxDynamicSharedMemorySize, (int)smemBytes);
    prettyrnn_kernel<<<blocks, NT, smemBytes>>>(
        anchors, n_jumps, positions, colors, markers,
        pre_W1, pre_b1, pre_b2,
        msg_W1, msg_b1, msg_b2,
        post_b1, post_b2,
        out_W1, out_b1, out_W2, out_b2,
        (float*)d_out);
}

// round 14
// speedup vs baseline: 1.0080x; 1.0080x over previous
#include <cuda_runtime.h>
#include <cuda_bf16.h>
#include <cstdint>
#include <math.h>

#define H 128
#define AP 136           // fp32 activation stride; 136 % 32 == 8 -> conflict-free LDS.64
#define NODES 32         // nodes per CTA
#define GPC 4            // graphs per CTA
#define NT 128
#define PXS 36           // packed-X row stride in uint4 (144 words = 16 mod 32 -> conflict-free)

// shared layout (float offsets)
#define OFF_A   0                        // fp32 A / s / h
#define OFF_B   (OFF_A + NODES*AP)       // 4352: fp32 pre1 out / B / upd / x
#define OFF_PX  (OFF_B + NODES*AP)       // 8704: packed X0 (uint4 fragments)
#define OFF_G   (OFF_PX + NODES*PXS*4)   // 13312: fp32 graph sums
#define OFF_POS (OFF_G + GPC*AP)         // 13856
#define OFF_D   (OFF_POS + NODES*2)      // 13920
#define OFF_INT (OFF_D + NODES*8)        // 14176
#define SMEM_FLOATS (OFF_INT + 80)       // 14256 floats = 57024 B -> 3 CTAs/SM, L1D ~57KB

// packed weights: 7 matrices x [kc(8)][c(128)][t(4)] entries of uint4 {bh01, bh89, bl01, bl89}
#define NMAT 7
#define MAT_ENTRIES (8 * 128 * 4)
__device__ uint4 g_Wpk[NMAT * MAT_ENTRIES];   // 448 KB

// ---- bf16 helpers ----
__device__ __forceinline__ uint32_t bpack(float lo, float hi) {   // lo -> bits[0:16), hi -> bits[16:32)
    uint32_t r;
    asm("cvt.rn.bf16x2.f32 %0, %1, %2;" : "=r"(r) : "f"(hi), "f"(lo));
    return r;
}
__device__ __forceinline__ float bf_lo(uint32_t p) { return __uint_as_float(p << 16); }
__device__ __forceinline__ float bf_hi(uint32_t p) { return __uint_as_float(p & 0xffff0000u); }

__device__ __forceinline__ void bsplit2(float2 v, uint32_t& h, uint32_t& l) {
    h = bpack(v.x, v.y);
    l = bpack(v.x - bf_lo(h), v.y - bf_hi(h));
}
__device__ __forceinline__ uint4 pack_entry(float v0, float v1, float v8, float v9) {
    uint32_t h01 = bpack(v0, v1);
    uint32_t l01 = bpack(v0 - bf_lo(h01), v1 - bf_hi(h01));
    uint32_t h89 = bpack(v8, v9);
    uint32_t l89 = bpack(v8 - bf_lo(h89), v9 - bf_hi(h89));
    return make_uint4(h01, h89, l01, l89);
}

// ---- prep kernel: pack weight matrices into mma-B-fragment order, pre-split bf16 hi/lo ----
__global__ void prep_weights_kernel(const float* __restrict__ pre_W2,
                                    const float* __restrict__ msg_W1,
                                    const float* __restrict__ msg_W2,
                                    const float* __restrict__ post_W1,
                                    const float* __restrict__ post_W2)
{
    int idx = blockIdx.x * blockDim.x + threadIdx.x;
    if (idx >= NMAT * MAT_ENTRIES) return;
    int t  = idx & 3;
    int c  = (idx >> 2) & 127;
    int kc = (idx >> 9) & 7;
    int m  = idx >> 12;

    const float* W;
    switch (m) {
        case 0: W = pre_W2; break;
        case 1: W = msg_W1; break;
        case 2: W = msg_W1 + H * H; break;
        case 3: W = msg_W2; break;
        case 4: W = post_W1; break;
        case 5: W = post_W1 + H * H; break;
        default: W = post_W2; break;
    }
    int k0 = kc * 16 + 2 * t;
    float w0 = W[(k0    ) * H + c];
    float w1 = W[(k0 + 1) * H + c];
    float w8 = W[(k0 + 8) * H + c];
    float w9 = W[(k0 + 9) * H + c];
    g_Wpk[idx] = pack_entry(w0, w1, w8, w9);
}

__device__ __forceinline__ void mma_bf16(float* c, const uint32_t* a, const uint32_t* b)
{
    asm volatile(
        "mma.sync.aligned.m16n8k16.row.col.f32.bf16.bf16.f32 "
        "{%0,%1,%2,%3}, {%4,%5,%6,%7}, {%8,%9}, {%0,%1,%2,%3};"
        : "+f"(c[0]), "+f"(c[1]), "+f"(c[2]), "+f"(c[3])
        : "r"(a[0]), "r"(a[1]), "r"(a[2]), "r"(a[3]), "r"(b[0]), "r"(b[1]));
}

// acc += X[32x128] @ W[128x128]; X fp32 in smem, W packed bf16 hi/lo in g_Wpk.
// 4 warps: warp w covers cols w*32..w*32+31, rows 0..31. 3xBF16 compensated.
// B-frags double-buffered in registers (prefetch kc+1 before kc's MMAs).
__device__ __forceinline__ void gemm_acc(const float* __restrict__ X,
                                         int mat, float acc[2][4][4])
{
    const uint4* __restrict__ Wp = g_Wpk + mat * MAT_ENTRIES;
    const int lane = threadIdx.x & 31;
    const int warp = threadIdx.x >> 5;
    const int n0 = warp * 32;
    const int g = lane >> 2, tig = lane & 3;

    uint4 bfr[4];
#pragma unroll
    for (int nt = 0; nt < 4; ++nt)
        bfr[nt] = __ldg(&Wp[(n0 + nt * 8 + g) * 4 + tig]);

#pragma unroll
    for (int kc = 0; kc < 8; ++kc) {
        uint4 bnx[4];
        if (kc < 7) {
#pragma unroll
            for (int nt = 0; nt < 4; ++nt)
                bnx[nt] = __ldg(&Wp[(((kc + 1) << 7) + n0 + nt * 8 + g) * 4 + tig]);
        }
        const int kk = kc * 16;
        uint32_t ah[2][4], al[2][4];
#pragma unroll
        for (int mt = 0; mt < 2; ++mt) {
            int r = mt * 16 + g;
            float2 a01 = *(const float2*)&X[ r      * AP + kk + 2 * tig];
            float2 c01 = *(const float2*)&X[(r + 8) * AP + kk + 2 * tig];
            float2 a89 = *(const float2*)&X[ r      * AP + kk + 2 * tig + 8];
            float2 c89 = *(const float2*)&X[(r + 8) * AP + kk + 2 * tig + 8];
            bsplit2(a01, ah[mt][0], al[mt][0]);
            bsplit2(c01, ah[mt][1], al[mt][1]);
            bsplit2(a89, ah[mt][2], al[mt][2]);
            bsplit2(c89, ah[mt][3], al[mt][3]);
        }
#pragma unroll
        for (int mt = 0; mt < 2; ++mt)
#pragma unroll
            for (int nt = 0; nt < 4; ++nt) {
                uint32_t bh[2] = {bfr[nt].x, bfr[nt].y};
                uint32_t bl[2] = {bfr[nt].z, bfr[nt].w};
                mma_bf16(acc[mt][nt], ah[mt], bh);
                mma_bf16(acc[mt][nt], al[mt], bh);
                mma_bf16(acc[mt][nt], ah[mt], bl);
            }
        if (kc < 7) {
#pragma unroll
            for (int nt = 0; nt < 4; ++nt) bfr[nt] = bnx[nt];
        }
    }
}

// packed-A variant: X pre-split in fragment order (uint4 {h01,h89,l01,l89}, stride PXS)
__device__ __forceinline__ void gemm_acc_pk(const uint4* __restrict__ PX,
                                            int mat, float acc[2][4][4])
{
    const uint4* __restrict__ Wp = g_Wpk + mat * MAT_ENTRIES;
    const int lane = threadIdx.x & 31;
    const int warp = threadIdx.x >> 5;
    const int n0 = warp * 32;
    const int g = lane >> 2, tig = lane & 3;

    uint4 bfr[4];
#pragma unroll
    for (int nt = 0; nt < 4; ++nt)
        bfr[nt] = __ldg(&Wp[(n0 + nt * 8 + g) * 4 + tig]);

#pragma unroll
    for (int kc = 0; kc < 8; ++kc) {
        uint4 bnx[4];
        if (kc < 7) {
#pragma unroll
            for (int nt = 0; nt < 4; ++nt)
                bnx[nt] = __ldg(&Wp[(((kc + 1) << 7) + n0 + nt * 8 + g) * 4 + tig]);
        }
        uint4 e0 = PX[(g     ) * PXS + kc * 4 + tig];
        uint4 e1 = PX[(g +  8) * PXS + kc * 4 + tig];
        uint4 e2 = PX[(g + 16) * PXS + kc * 4 + tig];
        uint4 e3 = PX[(g + 24) * PXS + kc * 4 + tig];
        uint32_t ah[2][4] = {{e0.x, e1.x, e0.y, e1.y}, {e2.x, e3.x, e2.y, e3.y}};
        uint32_t al[2][4] = {{e0.z, e1.z, e0.w, e1.w}, {e2.z, e3.z, e2.w, e3.w}};

#pragma unroll
        for (int mt = 0; mt < 2; ++mt)
#pragma unroll
            for (int nt = 0; nt < 4; ++nt) {
                uint32_t bh[2] = {bfr[nt].x, bfr[nt].y};
                uint32_t bl[2] = {bfr[nt].z, bfr[nt].w};
                mma_bf16(acc[mt][nt], ah[mt], bh);
                mma_bf16(acc[mt][nt], al[mt], bh);
                mma_bf16(acc[mt][nt], ah[mt], bl);
            }
        if (kc < 7) {
#pragma unroll
            for (int nt = 0; nt < 4; ++nt) bfr[nt] = bnx[nt];
        }
    }
}

// fp32 epilogue: float2 stores into stride-AP buffer
__device__ __forceinline__ void gemm_epi(float acc[2][4][4], float* __restrict__ C,
                                         const float* __restrict__ gbias, float biasScale,
                                         bool doRelu)
{
    const int lane = threadIdx.x & 31;
    const int warp = threadIdx.x >> 5;
    const int n0 = warp * 32;
    const int g = lane >> 2, tig = lane & 3;
#pragma unroll
    for (int nt = 0; nt < 4; ++nt) {
        int c = n0 + nt * 8 + 2 * tig;
        float2 bz = make_float2(0.f, 0.f);
        if (gbias) {
            float2 b = *(const float2*)&gbias[c];
            bz.x = biasScale * b.x; bz.y = biasScale * b.y;
        }
#pragma unroll
        for (int mt = 0; mt < 2; ++mt) {
            int r = mt * 16 + g;
#pragma unroll
            for (int h = 0; h < 2; ++h) {
                int rr = r + h * 8;
                float vx = acc[mt][nt][h * 2 + 0] + bz.x;
                float vy = acc[mt][nt][h * 2 + 1] + bz.y;
                if (doRelu) { vx = fmaxf(vx, 0.f); vy = fmaxf(vy, 0.f); }
                *(float2*)&C[rr * AP + c] = make_float2(vx, vy);
            }
        }
    }
}

// packed epilogue: store pre-split bf16 hi/lo fragments
__device__ __forceinline__ void gemm_epi_pk(float acc[2][4][4], uint4* __restrict__ PX,
                                            const float* __restrict__ gbias, float biasScale,
                                            bool doRelu)
{
    const int lane = threadIdx.x & 31;
    const int warp = threadIdx.x >> 5;
    const int n0 = warp * 32;
    const int g = lane >> 2, tig = lane & 3;

    float2 bz[4];
#pragma unroll
    for (int nt = 0; nt < 4; ++nt) {
        bz[nt] = make_float2(0.f, 0.f);
        if (gbias) {
            float2 b = *(const float2*)&gbias[n0 + nt * 8 + 2 * tig];
            bz[nt].x = biasScale * b.x; bz[nt].y = biasScale * b.y;
        }
    }
#pragma unroll
    for (int mt = 0; mt < 2; ++mt) {
#pragma unroll
        for (int h = 0; h < 2; ++h) {
            int rr = mt * 16 + h * 8 + g;
#pragma unroll
            for (int cc = 0; cc < 2; ++cc) {
                int ntA = 2 * cc, ntB = 2 * cc + 1;
                float v0x = acc[mt][ntA][h * 2 + 0] + bz[ntA].x;
                float v0y = acc[mt][ntA][h * 2 + 1] + bz[ntA].y;
                float v1x = acc[mt][ntB][h * 2 + 0] + bz[ntB].x;
                float v1y = acc[mt][ntB][h * 2 + 1] + bz[ntB].y;
                if (doRelu) {
                    v0x = fmaxf(v0x, 0.f); v0y = fmaxf(v0y, 0.f);
                    v1x = fmaxf(v1x, 0.f); v1y = fmaxf(v1y, 0.f);
                }
                PX[rr * PXS + (2 * warp + cc) * 4 + tig] = pack_entry(v0x, v0y, v1x, v1y);
            }
        }
    }
}

#define ACC_ZERO(acc) do {                                             \
    _Pragma("unroll")                                                  \
    for (int _m = 0; _m < 2; ++_m)                                     \
        _Pragma("unroll")                                              \
        for (int _n = 0; _n < 4; ++_n)                                 \
            _Pragma("unroll")                                          \
            for (int _i = 0; _i < 4; ++_i) acc[_m][_n][_i] = 0.f;      \
} while (0)

__global__ __launch_bounds__(NT, 3) void prettyrnn_kernel(
    const int* __restrict__ anchors, const int* __restrict__ n_jumps,
    const float* __restrict__ positions, const int* __restrict__ colors,
    const int* __restrict__ markers,
    const float* __restrict__ pre_W1, const float* __restrict__ pre_b1,
    const float* __restrict__ pre_b2,
    const float* __restrict__ msg_W1, const float* __restrict__ msg_b1,
    const float* __restrict__ msg_b2,
    const float* __restrict__ post_b1, const float* __restrict__ post_b2,
    const float* __restrict__ out_W1, const float* __restrict__ out_b1,
    const float* __restrict__ out_W2, const float* __restrict__ out_b2,
    float* __restrict__ out)
{
    extern __shared__ float sm[];
    float* sA  = sm + OFF_A;
    float* sB  = sm + OFF_B;
    uint4* sPX = (uint4*)(sm + OFF_PX);
    float* sG  = sm + OFF_G;
    float* sPos = sm + OFF_POS;
    float* sD  = sm + OFF_D;
    int* sCol = (int*)(sm + OFF_INT);
    int* sMrk = sCol + NODES;
    int* sAnc = sMrk + NODES;
    int* sJmp = sAnc + GPC;

    const int tid = threadIdx.x;
    const int lane = tid & 31;
    const int warp = tid >> 5;
    const int nodeBase = blockIdx.x * NODES;
    const int graphBase = blockIdx.x * GPC;
    const int tx = tid & 15;
    const int ty = tid >> 4;
    const int r0 = ty * 4;

    // ---- phase 0: per-node / per-graph inputs ----
    if (tid < NODES) {
        sCol[tid] = colors[nodeBase + tid];
        sMrk[tid] = markers[nodeBase + tid];
        sPos[2 * tid]     = positions[2 * (nodeBase + tid)];
        sPos[2 * tid + 1] = positions[2 * (nodeBase + tid) + 1];
    }
    if (tid >= NODES && tid < NODES + GPC) {
        int g = tid - NODES;
        sAnc[g] = anchors[graphBase + g];
        sJmp[g] = n_jumps[graphBase + g];
    }
    __syncthreads();

    // ---- distances ----
    for (int idx = tid; idx < NODES * 8; idx += NT) {
        int n = idx >> 3, jj = idx & 7;
        int j = (n & ~7) + jj;
        float dx = sPos[2 * n]     - sPos[2 * j];
        float dy = sPos[2 * n + 1] - sPos[2 * j + 1];
        sD[idx] = sqrtf(dx * dx + dy * dy);
    }

    // ---- pre layer 1 (coalesced gather): warp w -> rows 8w..8w+7, lane -> 4 consecutive cols ----
    {
        const float4* b1v = (const float4*)pre_b1;
#pragma unroll
        for (int r = 0; r < 8; ++r) {
            int n = warp * 8 + r;
            int g = n >> 3;
            float px = sPos[2 * n], py = sPos[2 * n + 1];
            const float4* rw0 = (const float4*)(pre_W1);
            const float4* rw1 = (const float4*)(pre_W1 + H);
            const float4* rc  = (const float4*)(pre_W1 + (2 + sCol[n]) * H);
            const float4* rm  = (const float4*)(pre_W1 + (10 + (sMrk[n] - 8)) * H);
            const float4* ra  = (const float4*)(pre_W1 + (18 + sAnc[g]) * H);
            const float4* rj  = (const float4*)(pre_W1 + (34 + sJmp[g]) * H);

            float4 vc = __ldg(&rc[lane]);
            float4 vm = __ldg(&rm[lane]);
            float4 va = __ldg(&ra[lane]);
            float4 vj = __ldg(&rj[lane]);
            float4 vb = __ldg(&b1v[lane]);
            float4 v0 = __ldg(&rw0[lane]);
            float4 v1 = __ldg(&rw1[lane]);

            float4 o;
            o.x = fmaxf(fmaf(px, v0.x, fmaf(py, v1.x, vc.x + vm.x + va.x + vj.x + vb.x)), 0.f);
            o.y = fmaxf(fmaf(px, v0.y, fmaf(py, v1.y, vc.y + vm.y + va.y + vj.y + vb.y)), 0.f);
            o.z = fmaxf(fmaf(px, v0.z, fmaf(py, v1.z, vc.z + vm.z + va.z + vj.z + vb.z)), 0.f);
            o.w = fmaxf(fmaf(px, v0.w, fmaf(py, v1.w, vc.w + vm.w + va.w + vj.w + vb.w)), 0.f);
            *(float4*)&sA[n * AP + 4 * lane] = o;
        }
    }
    __syncthreads();

    // ---- pre layer 2 (linear): x0 = h1 @ pre_W2 + b2 -> sPX (packed) ----
    {
        float acc[2][4][4]; ACC_ZERO(acc);
        gemm_acc(sA, 0, acc);
        gemm_epi_pk(acc, sPX, pre_b2, 1.f, false);
    }
    __syncthreads();

    // ---- A = x0 @ msg_W1[0:128] -> sA ; B = x0 @ msg_W1[128:256] -> sB ----
    {
        float acc[2][4][4]; ACC_ZERO(acc);
        gemm_acc_pk(sPX, 1, acc);
        gemm_epi(acc, sA, nullptr, 0.f, false);
    }
    {
        float acc[2][4][4]; ACC_ZERO(acc);
        gemm_acc_pk(sPX, 2, acc);
        gemm_epi(acc, sB, nullptr, 0.f, false);
    }
    __syncthreads();

    // ---- edge aggregation (register-blocked, conflict-free strips):
    //      thread owns cols {tx*4..+3, tx*4+64..+67} of its 4 rows; loads the 8 octet
    //      B-rows once per strip. s[n] = sum_{j!=n} relu(A[n]+B[j]+d*w1d+b1) -> sA
    {
        const float* w1d = msg_W1 + 2 * H * H;
        const int octet = r0 & ~7;
#pragma unroll
        for (int half = 0; half < 2; ++half) {
            const int cb = tx * 4 + half * 64;
            float4 wv = __ldg((const float4*)&w1d[cb]);
            float4 bv = __ldg((const float4*)&msg_b1[cb]);
            float4 Brow[8];
#pragma unroll
            for (int j = 0; j < 8; ++j)
                Brow[j] = *(const float4*)&sB[(octet + j) * AP + cb];
#pragma unroll
            for (int i = 0; i < 4; ++i) {
                int n = r0 + i, nloc = n & 7;
                float4 a = *(const float4*)&sA[n * AP + cb];
                float4 s = make_float4(0.f, 0.f, 0.f, 0.f);
#pragma unroll
                for (int jj = 0; jj < 8; ++jj) {
                    if (jj == nloc) continue;
                    float d = sD[n * 8 + jj];
                    s.x += fmaxf(a.x + Brow[jj].x + fmaf(d, wv.x, bv.x), 0.f);
                    s.y += fmaxf(a.y + Brow[jj].y + fmaf(d, wv.y, bv.y), 0.f);
                    s.z += fmaxf(a.z + Brow[jj].z + fmaf(d, wv.z, bv.z), 0.f);
                    s.w += fmaxf(a.w + Brow[jj].w + fmaf(d, wv.w, bv.w), 0.f);
                }
                *(float4*)&sA[n * AP + cb] = s;
            }
        }
    }
    __syncthreads();

    // ---- upd = s @ msg_W2 + 7*msg_b2 -> sB ----
    {
        float acc[2][4][4]; ACC_ZERO(acc);
        gemm_acc(sA, 3, acc);
        gemm_epi(acc, sB, msg_b2, 7.f, false);
    }
    __syncthreads();

    // ---- post layer 1 (fused 2K): h = relu(upd@P1a + x0@P1b + b1) -> sA ----
    {
        float acc[2][4][4]; ACC_ZERO(acc);
        gemm_acc(sB, 4, acc);
        gemm_acc_pk(sPX, 5, acc);
        gemm_epi(acc, sA, post_b1, 1.f, true);
    }
    __syncthreads();

    // ---- post layer 2: x = h @ post_W2 + b2 -> sB ----
    {
        float acc[2][4][4]; ACC_ZERO(acc);
        gemm_acc(sA, 6, acc);
        gemm_epi(acc, sB, post_b2, 1.f, false);
    }
    __syncthreads();

    // ---- graph sum -> sG ----
    for (int idx = tid; idx < GPC * H; idx += NT) {
        int g = idx >> 7, k = idx & (H - 1);
        float s = 0.f;
#pragma unroll
        for (int i = 0; i < 8; ++i) s += sB[(g * 8 + i) * AP + k];
        sG[g * AP + k] = s;
    }
    __syncthreads();

    // ---- out layer 1 (SIMT): col k=tid fixed per thread ----
    {
        float s0 = __ldg(&out_b1[tid]);
        float s1 = s0, s2 = s0, s3 = s0;
#pragma unroll 4
        for (int kk = 0; kk < H; ++kk) {
            float w = __ldg(&out_W1[kk * H + tid]);
            s0 = fmaf(sG[0 * AP + kk], w, s0);
            s1 = fmaf(sG[1 * AP + kk], w, s1);
            s2 = fmaf(sG[2 * AP + kk], w, s2);
            s3 = fmaf(sG[3 * AP + kk], w, s3);
        }
        sA[0 * AP + tid] = fmaxf(s0, 0.f);
        sA[1 * AP + tid] = fmaxf(s1, 0.f);
        sA[2 * AP + tid] = fmaxf(s2, 0.f);
        sA[3 * AP + tid] = fmaxf(s3, 0.f);
    }
    __syncthreads();

    // ---- out layer 2 (SIMT): logits -> gmem ----
    if (tid < GPC * 16) {
        int g = tid >> 4, o = tid & 15;
        float s = __ldg(&out_b2[o]);
#pragma unroll 8
        for (int k = 0; k < H; ++k)
            s = fmaf(sA[g * AP + k], __ldg(&out_W2[k * 16 + o]), s);
        out[(graphBase + g) * 16 + o] = s;
    }
}

extern "C" void kernel_launch(void* const* d_in, const int* in_sizes, int n_in,
                              void* d_out, int out_size)
{
    const int*   anchors   = (const int*)d_in[0];
    const int*   n_jumps   = (const int*)d_in[1];
    const float* positions = (const float*)d_in[2];
    const int*   colors    = (const int*)d_in[3];
    const int*   markers   = (const int*)d_in[4];
    const float* pre_W1  = (const float*)d_in[5];
    const float* pre_b1  = (const float*)d_in[6];
    const float* pre_W2  = (const float*)d_in[7];
    const float* pre_b2  = (const float*)d_in[8];
    const float* msg_W1  = (const float*)d_in[9];
    const float* msg_b1  = (const float*)d_in[10];
    const float* msg_W2  = (const float*)d_in[11];
    const float* msg_b2  = (const float*)d_in[12];
    const float* post_W1 = (const float*)d_in[13];
    const float* post_b1 = (const float*)d_in[14];
    const float* post_W2 = (const float*)d_in[15];
    const float* post_b2 = (const float*)d_in[16];
    const float* out_W1  = (const float*)d_in[17];
    const float* out_b1  = (const float*)d_in[18];
    const float* out_W2  = (const float*)d_in[19];
    const float* out_b2  = (const float*)d_in[20];

    // 1) pack + pre-split weights (same every call: deterministic, graph-capturable)
    int prepThreads = NMAT * MAT_ENTRIES;
    prep_weights_kernel<<<(prepThreads + 255) / 256, 256>>>(
        pre_W2, msg_W1, msg_W2, post_W1, post_W2);

    // 2) main fused kernel
    int bs = in_sizes[0];
    int blocks = bs / GPC;
    size_t smemBytes = SMEM_FLOATS * sizeof(float);
    cudaFuncSetAttribute(prettyrnn_kernel,
                         cudaFuncAttributeMaxDynamicSharedMemorySize, (int)smemBytes);
    prettyrnn_kernel<<<blocks, NT, smemBytes>>>(
        anchors, n_jumps, positions, colors, markers,
        pre_W1, pre_b1, pre_b2,
        msg_W1, msg_b1, msg_b2,
        post_b1, post_b2,
        out_W1, out_b1, out_W2, out_b2,
        (float*)d_out);
}

// round 15
// speedup vs baseline: 1.2181x; 1.2084x over previous
#include <cuda_runtime.h>
#include <cuda_bf16.h>
#include <cstdint>
#include <math.h>

#define H 128
#define AP 136           // fp32 activation stride; 136 % 32 == 8 -> conflict-free LDS.64
#define NODES 32         // nodes per CTA
#define GPC 4            // graphs per CTA
#define NT 128

// shared layout (float offsets)
#define OFF_H   0                        // fp32 h1 (alive across whole kernel)
#define OFF_A   (OFF_H + NODES*AP)       // 4352: fp32 A / s / x
#define OFF_B   (OFF_A + NODES*AP)       // 8704: fp32 B / h
#define OFF_G   (OFF_B + NODES*AP)       // 13056: fp32 graph sums
#define OFF_POS (OFF_G + GPC*AP)         // 13600
#define OFF_D   (OFF_POS + NODES*2)      // 13664
#define OFF_INT (OFF_D + NODES*8)        // 13920
#define SMEM_FLOATS (OFF_INT + 80)       // 14000 floats = 56000 B -> 4 CTAs/SM

// packed weights: 5 matrices x [kc(8)][c(128)][t(4)] entries of uint4 {bh01, bh89, bl01, bl89}
// 0: W_A = pre_W2 @ M1a      1: W_B = pre_W2 @ M1b
// 2: W_SP = msg_W2 @ P1a     3: W_XP = pre_W2 @ P1b     4: post_W2
#define NMAT 5
#define MAT_ENTRIES (8 * 128 * 4)
__device__ uint4 g_Wpk[NMAT * MAT_ENTRIES];        // 320 KB
__device__ float g_Wf[4 * H * H];                  // fp32 fused matrices (prep intermediate)
__device__ __align__(16) float g_bias[3 * H];      // bA, bB, bh

// ---- bf16 helpers ----
__device__ __forceinline__ uint32_t bpack(float lo, float hi) {   // lo -> bits[0:16), hi -> bits[16:32)
    uint32_t r;
    asm("cvt.rn.bf16x2.f32 %0, %1, %2;" : "=r"(r) : "f"(hi), "f"(lo));
    return r;
}
__device__ __forceinline__ float bf_lo(uint32_t p) { return __uint_as_float(p << 16); }
__device__ __forceinline__ float bf_hi(uint32_t p) { return __uint_as_float(p & 0xffff0000u); }

__device__ __forceinline__ void bsplit2(float2 v, uint32_t& h, uint32_t& l) {
    h = bpack(v.x, v.y);
    l = bpack(v.x - bf_lo(h), v.y - bf_hi(h));
}
__device__ __forceinline__ uint4 pack_entry(float v0, float v1, float v8, float v9) {
    uint32_t h01 = bpack(v0, v1);
    uint32_t l01 = bpack(v0 - bf_lo(h01), v1 - bf_hi(h01));
    uint32_t h89 = bpack(v8, v9);
    uint32_t l89 = bpack(v8 - bf_lo(h89), v9 - bf_hi(h89));
    return make_uint4(h01, h89, l01, l89);
}

// ---- prep 1: fused fp32 weight products ----
// g_Wf[m] = L @ R   (all [128,128] row-major: out[k][c] = sum_j L[k][j]*R[j][c])
__global__ void prep_fuse_kernel(const float* __restrict__ pre_W2,
                                 const float* __restrict__ msg_W1,
                                 const float* __restrict__ msg_W2,
                                 const float* __restrict__ post_W1)
{
    int idx = blockIdx.x * blockDim.x + threadIdx.x;
    if (idx >= 4 * H * H) return;
    int m = idx >> 14;
    int k = (idx >> 7) & 127;
    int c = idx & 127;
    const float* L = (m == 2) ? msg_W2 : pre_W2;
    const float* R;
    switch (m) {
        case 0: R = msg_W1; break;              // M1a
        case 1: R = msg_W1 + H * H; break;      // M1b
        case 2: R = post_W1; break;             // P1a
        default: R = post_W1 + H * H; break;    // P1b
    }
    float s = 0.f;
#pragma unroll 8
    for (int j = 0; j < H; ++j)
        s = fmaf(__ldg(&L[k * H + j]), __ldg(&R[j * H + c]), s);
    g_Wf[idx] = s;
}

// ---- prep 2: fused bias vectors ----
// bA = pre_b2@M1a ; bB = pre_b2@M1b ; bh = 7*msg_b2@P1a + pre_b2@P1b + post_b1
__global__ void prep_bias_kernel(const float* __restrict__ pre_b2,
                                 const float* __restrict__ msg_W1,
                                 const float* __restrict__ msg_b2,
                                 const float* __restrict__ post_W1,
                                 const float* __restrict__ post_b1)
{
    int c = threadIdx.x;
    if (c >= H) return;
    float bA = 0.f, bB = 0.f, bh = 0.f;
#pragma unroll 4
    for (int k = 0; k < H; ++k) {
        float p2 = __ldg(&pre_b2[k]);
        bA = fmaf(p2, __ldg(&msg_W1[k * H + c]), bA);
        bB = fmaf(p2, __ldg(&msg_W1[H * H + k * H + c]), bB);
        bh = fmaf(7.f * __ldg(&msg_b2[k]), __ldg(&post_W1[k * H + c]), bh);
        bh = fmaf(p2, __ldg(&post_W1[H * H + k * H + c]), bh);
    }
    g_bias[c]         = bA;
    g_bias[H + c]     = bB;
    g_bias[2 * H + c] = bh + __ldg(&post_b1[c]);
}

// ---- prep 3: pack 5 matrices (4 fused + post_W2) into mma-B-fragment order ----
__global__ void prep_pack_kernel(const float* __restrict__ post_W2)
{
    int idx = blockIdx.x * blockDim.x + threadIdx.x;
    if (idx >= NMAT * MAT_ENTRIES) return;
    int t  = idx & 3;
    int c  = (idx >> 2) & 127;
    int kc = (idx >> 9) & 7;
    int m  = idx >> 12;

    const float* W = (m < 4) ? (g_Wf + m * H * H) : post_W2;
    int k0 = kc * 16 + 2 * t;
    float w0 = W[(k0    ) * H + c];
    float w1 = W[(k0 + 1) * H + c];
    float w8 = W[(k0 + 8) * H + c];
    float w9 = W[(k0 + 9) * H + c];
    g_Wpk[idx] = pack_entry(w0, w1, w8, w9);
}

__device__ __forceinline__ void mma_bf16(float* c, const uint32_t* a, const uint32_t* b)
{
    asm volatile(
        "mma.sync.aligned.m16n8k16.row.col.f32.bf16.bf16.f32 "
        "{%0,%1,%2,%3}, {%4,%5,%6,%7}, {%8,%9}, {%0,%1,%2,%3};"
        : "+f"(c[0]), "+f"(c[1]), "+f"(c[2]), "+f"(c[3])
        : "r"(a[0]), "r"(a[1]), "r"(a[2]), "r"(a[3]), "r"(b[0]), "r"(b[1]));
}

// acc += X[32x128] @ W[128x128]; X fp32 in smem (stride AP), W packed bf16 hi/lo in g_Wpk.
// 4 warps: warp w covers cols w*32..w*32+31, rows 0..31. 3xBF16 compensated (hh+lh+hl).
__device__ __forceinline__ void gemm_acc(const float* __restrict__ X,
                                         int mat, float acc[2][4][4])
{
    const uint4* __restrict__ Wp = g_Wpk + mat * MAT_ENTRIES;
    const int lane = threadIdx.x & 31;
    const int warp = threadIdx.x >> 5;
    const int n0 = warp * 32;
    const int g = lane >> 2, tig = lane & 3;

#pragma unroll
    for (int kc = 0; kc < 8; ++kc) {
        const int kk = kc * 16;
        uint4 bfr[4];
#pragma unroll
        for (int nt = 0; nt < 4; ++nt)
            bfr[nt] = __ldg(&Wp[((kc << 7) + n0 + nt * 8 + g) * 4 + tig]);

        uint32_t ah[2][4], al[2][4];
#pragma unroll
        for (int mt = 0; mt < 2; ++mt) {
            int r = mt * 16 + g;
            float2 a01 = *(const float2*)&X[ r      * AP + kk + 2 * tig];
            float2 c01 = *(const float2*)&X[(r + 8) * AP + kk + 2 * tig];
            float2 a89 = *(const float2*)&X[ r      * AP + kk + 2 * tig + 8];
            float2 c89 = *(const float2*)&X[(r + 8) * AP + kk + 2 * tig + 8];
            bsplit2(a01, ah[mt][0], al[mt][0]);
            bsplit2(c01, ah[mt][1], al[mt][1]);
            bsplit2(a89, ah[mt][2], al[mt][2]);
            bsplit2(c89, ah[mt][3], al[mt][3]);
        }
#pragma unroll
        for (int mt = 0; mt < 2; ++mt)
#pragma unroll
            for (int nt = 0; nt < 4; ++nt) {
                uint32_t bh[2] = {bfr[nt].x, bfr[nt].y};
                uint32_t bl[2] = {bfr[nt].z, bfr[nt].w};
                mma_bf16(acc[mt][nt], ah[mt], bh);
                mma_bf16(acc[mt][nt], al[mt], bh);
                mma_bf16(acc[mt][nt], ah[mt], bl);
            }
    }
}

// fp32 epilogue: float2 stores into stride-AP buffer
__device__ __forceinline__ void gemm_epi(float acc[2][4][4], float* __restrict__ C,
                                         const float* __restrict__ gbias, bool doRelu)
{
    const int lane = threadIdx.x & 31;
    const int warp = threadIdx.x >> 5;
    const int n0 = warp * 32;
    const int g = lane >> 2, tig = lane & 3;
#pragma unroll
    for (int nt = 0; nt < 4; ++nt) {
        int c = n0 + nt * 8 + 2 * tig;
        float2 bz = make_float2(0.f, 0.f);
        if (gbias) bz = *(const float2*)&gbias[c];
#pragma unroll
        for (int mt = 0; mt < 2; ++mt) {
            int r = mt * 16 + g;
#pragma unroll
            for (int h = 0; h < 2; ++h) {
                int rr = r + h * 8;
                float vx = acc[mt][nt][h * 2 + 0] + bz.x;
                float vy = acc[mt][nt][h * 2 + 1] + bz.y;
                if (doRelu) { vx = fmaxf(vx, 0.f); vy = fmaxf(vy, 0.f); }
                *(float2*)&C[rr * AP + c] = make_float2(vx, vy);
            }
        }
    }
}

#define ACC_ZERO(acc) do {                                             \
    _Pragma("unroll")                                                  \
    for (int _m = 0; _m < 2; ++_m)                                     \
        _Pragma("unroll")                                              \
        for (int _n = 0; _n < 4; ++_n)                                 \
            _Pragma("unroll")                                          \
            for (int _i = 0; _i < 4; ++_i) acc[_m][_n][_i] = 0.f;      \
} while (0)

__global__ __launch_bounds__(NT, 4) void prettyrnn_kernel(
    const int* __restrict__ anchors, const int* __restrict__ n_jumps,
    const float* __restrict__ positions, const int* __restrict__ colors,
    const int* __restrict__ markers,
    const float* __restrict__ pre_W1, const float* __restrict__ pre_b1,
    const float* __restrict__ msg_W1, const float* __restrict__ msg_b1,
    const float* __restrict__ post_b2,
    const float* __restrict__ out_W1, const float* __restrict__ out_b1,
    const float* __restrict__ out_W2, const float* __restrict__ out_b2,
    float* __restrict__ out)
{
    extern __shared__ float sm[];
    float* sH  = sm + OFF_H;
    float* sA  = sm + OFF_A;
    float* sB  = sm + OFF_B;
    float* sG  = sm + OFF_G;
    float* sPos = sm + OFF_POS;
    float* sD  = sm + OFF_D;
    int* sCol = (int*)(sm + OFF_INT);
    int* sMrk = sCol + NODES;
    int* sAnc = sMrk + NODES;
    int* sJmp = sAnc + GPC;

    const int tid = threadIdx.x;
    const int lane = tid & 31;
    const int warp = tid >> 5;
    const int nodeBase = blockIdx.x * NODES;
    const int graphBase = blockIdx.x * GPC;
    const int tx = tid & 15;
    const int ty = tid >> 4;
    const int r0 = ty * 4;

    // ---- phase 0: per-node / per-graph inputs ----
    if (tid < NODES) {
        sCol[tid] = colors[nodeBase + tid];
        sMrk[tid] = markers[nodeBase + tid];
        sPos[2 * tid]     = positions[2 * (nodeBase + tid)];
        sPos[2 * tid + 1] = positions[2 * (nodeBase + tid) + 1];
    }
    if (tid >= NODES && tid < NODES + GPC) {
        int g = tid - NODES;
        sAnc[g] = anchors[graphBase + g];
        sJmp[g] = n_jumps[graphBase + g];
    }
    __syncthreads();

    // ---- distances ----
    for (int idx = tid; idx < NODES * 8; idx += NT) {
        int n = idx >> 3, jj = idx & 7;
        int j = (n & ~7) + jj;
        float dx = sPos[2 * n]     - sPos[2 * j];
        float dy = sPos[2 * n + 1] - sPos[2 * j + 1];
        sD[idx] = sqrtf(dx * dx + dy * dy);
    }

    // ---- pre layer 1 (coalesced gather): warp w -> rows 8w..8w+7, lane -> 4 consecutive cols ----
    {
        const float4* b1v = (const float4*)pre_b1;
#pragma unroll
        for (int r = 0; r < 8; ++r) {
            int n = warp * 8 + r;
            int g = n >> 3;
            float px = sPos[2 * n], py = sPos[2 * n + 1];
            const float4* rw0 = (const float4*)(pre_W1);
            const float4* rw1 = (const float4*)(pre_W1 + H);
            const float4* rc  = (const float4*)(pre_W1 + (2 + sCol[n]) * H);
            const float4* rm  = (const float4*)(pre_W1 + (10 + (sMrk[n] - 8)) * H);
            const float4* ra  = (const float4*)(pre_W1 + (18 + sAnc[g]) * H);
            const float4* rj  = (const float4*)(pre_W1 + (34 + sJmp[g]) * H);

            float4 vc = __ldg(&rc[lane]);
            float4 vm = __ldg(&rm[lane]);
            float4 va = __ldg(&ra[lane]);
            float4 vj = __ldg(&rj[lane]);
            float4 vb = __ldg(&b1v[lane]);
            float4 v0 = __ldg(&rw0[lane]);
            float4 v1 = __ldg(&rw1[lane]);

            float4 o;
            o.x = fmaxf(fmaf(px, v0.x, fmaf(py, v1.x, vc.x + vm.x + va.x + vj.x + vb.x)), 0.f);
            o.y = fmaxf(fmaf(px, v0.y, fmaf(py, v1.y, vc.y + vm.y + va.y + vj.y + vb.y)), 0.f);
            o.z = fmaxf(fmaf(px, v0.z, fmaf(py, v1.z, vc.z + vm.z + va.z + vj.z + vb.z)), 0.f);
            o.w = fmaxf(fmaf(px, v0.w, fmaf(py, v1.w, vc.w + vm.w + va.w + vj.w + vb.w)), 0.f);
            *(float4*)&sH[n * AP + 4 * lane] = o;
        }
    }
    __syncthreads();

    // ---- A = h1 @ W_A + bA -> sA ; B = h1 @ W_B + bB -> sB  (x0 fused away) ----
    {
        float acc[2][4][4]; ACC_ZERO(acc);
        gemm_acc(sH, 0, acc);
        gemm_epi(acc, sA, g_bias, false);
    }
    {
        float acc[2][4][4]; ACC_ZERO(acc);
        gemm_acc(sH, 1, acc);
        gemm_epi(acc, sB, g_bias + H, false);
    }
    __syncthreads();

    // ---- edge aggregation (register-blocked, conflict-free strips):
    //      thread owns cols {tx*4..+3, tx*4+64..+67} of its 4 rows.
    //      s[n] = sum_{j!=n} relu(A[n]+B[j]+d*w1d+b1) -> sA
    {
        const float* w1d = msg_W1 + 2 * H * H;
        const int octet = r0 & ~7;
#pragma unroll
        for (int half = 0; half < 2; ++half) {
            const int cb = tx * 4 + half * 64;
            float4 wv = __ldg((const float4*)&w1d[cb]);
            float4 bv = __ldg((const float4*)&msg_b1[cb]);
            float4 Brow[8];
#pragma unroll
            for (int j = 0; j < 8; ++j)
                Brow[j] = *(const float4*)&sB[(octet + j) * AP + cb];
#pragma unroll
            for (int i = 0; i < 4; ++i) {
                int n = r0 + i, nloc = n & 7;
                float4 a = *(const float4*)&sA[n * AP + cb];
                float4 s = make_float4(0.f, 0.f, 0.f, 0.f);
#pragma unroll
                for (int jj = 0; jj < 8; ++jj) {
                    if (jj == nloc) continue;
                    float d = sD[n * 8 + jj];
                    s.x += fmaxf(a.x + Brow[jj].x + fmaf(d, wv.x, bv.x), 0.f);
                    s.y += fmaxf(a.y + Brow[jj].y + fmaf(d, wv.y, bv.y), 0.f);
                    s.z += fmaxf(a.z + Brow[jj].z + fmaf(d, wv.z, bv.z), 0.f);
                    s.w += fmaxf(a.w + Brow[jj].w + fmaf(d, wv.w, bv.w), 0.f);
                }
                *(float4*)&sA[n * AP + cb] = s;
            }
        }
    }
    __syncthreads();

    // ---- post layer 1 (fused, upd eliminated): h = relu(s@W_SP + h1@W_XP + bh) -> sB ----
    {
        float acc[2][4][4]; ACC_ZERO(acc);
        gemm_acc(sA, 2, acc);
        gemm_acc(sH, 3, acc);
        gemm_epi(acc, sB, g_bias + 2 * H, true);
    }
    __syncthreads();

    // ---- post layer 2: x = h @ post_W2 + post_b2 -> sA ----
    {
        float acc[2][4][4]; ACC_ZERO(acc);
        gemm_acc(sB, 4, acc);
        gemm_epi(acc, sA, post_b2, false);
    }
    __syncthreads();

    // ---- graph sum -> sG ----
    for (int idx = tid; idx < GPC * H; idx += NT) {
        int g = idx >> 7, k = idx & (H - 1);
        float s = 0.f;
#pragma unroll
        for (int i = 0; i < 8; ++i) s += sA[(g * 8 + i) * AP + k];
        sG[g * AP + k] = s;
    }
    __syncthreads();

    // ---- out layer 1 (SIMT): col k=tid fixed per thread -> sB rows 0..3 ----
    {
        float s0 = __ldg(&out_b1[tid]);
        float s1 = s0, s2 = s0, s3 = s0;
#pragma unroll 4
        for (int kk = 0; kk < H; ++kk) {
            float w = __ldg(&out_W1[kk * H + tid]);
            s0 = fmaf(sG[0 * AP + kk], w, s0);
            s1 = fmaf(sG[1 * AP + kk], w, s1);
            s2 = fmaf(sG[2 * AP + kk], w, s2);
            s3 = fmaf(sG[3 * AP + kk], w, s3);
        }
        sB[0 * AP + tid] = fmaxf(s0, 0.f);
        sB[1 * AP + tid] = fmaxf(s1, 0.f);
        sB[2 * AP + tid] = fmaxf(s2, 0.f);
        sB[3 * AP + tid] = fmaxf(s3, 0.f);
    }
    __syncthreads();

    // ---- out layer 2 (SIMT): logits -> gmem ----
    if (tid < GPC * 16) {
        int g = tid >> 4, o = tid & 15;
        float s = __ldg(&out_b2[o]);
#pragma unroll 8
        for (int k = 0; k < H; ++k)
            s = fmaf(sB[g * AP + k], __ldg(&out_W2[k * 16 + o]), s);
        out[(graphBase + g) * 16 + o] = s;
    }
}

extern "C" void kernel_launch(void* const* d_in, const int* in_sizes, int n_in,
                              void* d_out, int out_size)
{
    const int*   anchors   = (const int*)d_in[0];
    const int*   n_jumps   = (const int*)d_in[1];
    const float* positions = (const float*)d_in[2];
    const int*   colors    = (const int*)d_in[3];
    const int*   markers   = (const int*)d_in[4];
    const float* pre_W1  = (const float*)d_in[5];
    const float* pre_b1  = (const float*)d_in[6];
    const float* pre_W2  = (const float*)d_in[7];
    const float* pre_b2  = (const float*)d_in[8];
    const float* msg_W1  = (const float*)d_in[9];
    const float* msg_b1  = (const float*)d_in[10];
    const float* msg_W2  = (const float*)d_in[11];
    const float* msg_b2  = (const float*)d_in[12];
    const float* post_W1 = (const float*)d_in[13];
    const float* post_b1 = (const float*)d_in[14];
    const float* post_W2 = (const float*)d_in[15];
    const float* post_b2 = (const float*)d_in[16];
    const float* out_W1  = (const float*)d_in[17];
    const float* out_b1  = (const float*)d_in[18];
    const float* out_W2  = (const float*)d_in[19];
    const float* out_b2  = (const float*)d_in[20];

    // prep chain (deterministic, graph-capturable; sequential on stream)
    prep_fuse_kernel<<<(4 * H * H + 255) / 256, 256>>>(pre_W2, msg_W1, msg_W2, post_W1);
    prep_bias_kernel<<<1, H>>>(pre_b2, msg_W1, msg_b2, post_W1, post_b1);
    prep_pack_kernel<<<(NMAT * MAT_ENTRIES + 255) / 256, 256>>>(post_W2);

    // main fused kernel
    int bs = in_sizes[0];
    int blocks = bs / GPC;
    size_t smemBytes = SMEM_FLOATS * sizeof(float);
    cudaFuncSetAttribute(prettyrnn_kernel,
                         cudaFuncAttributeMaxDynamicSharedMemorySize, (int)smemBytes);
    prettyrnn_kernel<<<blocks, NT, smemBytes>>>(
        anchors, n_jumps, positions, colors, markers,
        pre_W1, pre_b1,
        msg_W1, msg_b1,
        post_b2,
        out_W1, out_b1, out_W2, out_b2,
        (float*)d_out);
}

// round 16
// speedup vs baseline: 1.2954x; 1.0635x over previous
#include <cuda_runtime.h>
#include <cuda_bf16.h>
#include <cstdint>
#include <math.h>

#define H 128
#define AP 136           // fp32 activation stride; 136 % 32 == 8 -> conflict-free LDS.64
#define NODES 32         // nodes per CTA
#define GPC 4            // graphs per CTA
#define NT 128

// shared layout (float offsets)
#define OFF_H   0                        // fp32 h1 (alive across whole kernel)
#define OFF_A   (OFF_H + NODES*AP)       // 4352: fp32 A / s
#define OFF_B   (OFF_A + NODES*AP)       // 8704: fp32 B / h
#define OFF_G   (OFF_B + NODES*AP)       // 13056: fp32 graph sums of h
#define OFF_POS (OFF_G + GPC*AP)         // 13600
#define OFF_D   (OFF_POS + NODES*2)      // 13664
#define OFF_INT (OFF_D + NODES*8)        // 13920
#define SMEM_FLOATS (OFF_INT + 80)       // 14000 floats = 56000 B -> 4 CTAs/SM

// packed weights: 4 matrices x [kc(8)][c(128)][t(4)] entries of uint4 {bh01, bh89, bl01, bl89}
// 0: W_A = pre_W2 @ M1a      1: W_B = pre_W2 @ M1b
// 2: W_SP = msg_W2 @ P1a     3: W_XP = pre_W2 @ P1b
#define NMAT 4
#define MAT_ENTRIES (8 * 128 * 4)
__device__ uint4 g_Wpk[NMAT * MAT_ENTRIES];        // 256 KB
__device__ float g_Wf[5 * H * H];                  // fp32 fused matrices; [4] = W_PO = post_W2@out_W1
__device__ __align__(16) float g_bias[4 * H];      // bA, bB, bh, bO

// ---- bf16 helpers ----
__device__ __forceinline__ uint32_t bpack(float lo, float hi) {   // lo -> bits[0:16), hi -> bits[16:32)
    uint32_t r;
    asm("cvt.rn.bf16x2.f32 %0, %1, %2;" : "=r"(r) : "f"(hi), "f"(lo));
    return r;
}
__device__ __forceinline__ float bf_lo(uint32_t p) { return __uint_as_float(p << 16); }
__device__ __forceinline__ float bf_hi(uint32_t p) { return __uint_as_float(p & 0xffff0000u); }

__device__ __forceinline__ void bsplit2(float2 v, uint32_t& h, uint32_t& l) {
    h = bpack(v.x, v.y);
    l = bpack(v.x - bf_lo(h), v.y - bf_hi(h));
}
__device__ __forceinline__ uint4 pack_entry(float v0, float v1, float v8, float v9) {
    uint32_t h01 = bpack(v0, v1);
    uint32_t l01 = bpack(v0 - bf_lo(h01), v1 - bf_hi(h01));
    uint32_t h89 = bpack(v8, v9);
    uint32_t l89 = bpack(v8 - bf_lo(h89), v9 - bf_hi(h89));
    return make_uint4(h01, h89, l01, l89);
}

// ---- prep 1: fused fp32 weight products ----
// g_Wf[m] = L @ R   (all [128,128] row-major: out[k][c] = sum_j L[k][j]*R[j][c])
__global__ void prep_fuse_kernel(const float* __restrict__ pre_W2,
                                 const float* __restrict__ msg_W1,
                                 const float* __restrict__ msg_W2,
                                 const float* __restrict__ post_W1,
                                 const float* __restrict__ post_W2,
                                 const float* __restrict__ out_W1)
{
    int idx = blockIdx.x * blockDim.x + threadIdx.x;
    if (idx >= 5 * H * H) return;
    int m = idx >> 14;
    int k = (idx >> 7) & 127;
    int c = idx & 127;
    const float* L;
    const float* R;
    switch (m) {
        case 0: L = pre_W2;  R = msg_W1; break;              // W_A
        case 1: L = pre_W2;  R = msg_W1 + H * H; break;      // W_B
        case 2: L = msg_W2;  R = post_W1; break;             // W_SP
        case 3: L = pre_W2;  R = post_W1 + H * H; break;     // W_XP
        default: L = post_W2; R = out_W1; break;             // W_PO
    }
    float s = 0.f;
#pragma unroll 8
    for (int j = 0; j < H; ++j)
        s = fmaf(__ldg(&L[k * H + j]), __ldg(&R[j * H + c]), s);
    g_Wf[idx] = s;
}

// ---- prep 2: fused bias vectors ----
// bA = pre_b2@M1a ; bB = pre_b2@M1b ; bh = 7*msg_b2@P1a + pre_b2@P1b + post_b1
// bO = 8*post_b2@out_W1 + out_b1
__global__ void prep_bias_kernel(const float* __restrict__ pre_b2,
                                 const float* __restrict__ msg_W1,
                                 const float* __restrict__ msg_b2,
                                 const float* __restrict__ post_W1,
                                 const float* __restrict__ post_b1,
                                 const float* __restrict__ post_b2,
                                 const float* __restrict__ out_W1,
                                 const float* __restrict__ out_b1)
{
    int c = threadIdx.x;
    if (c >= H) return;
    float bA = 0.f, bB = 0.f, bh = 0.f, bO = 0.f;
#pragma unroll 4
    for (int k = 0; k < H; ++k) {
        float p2 = __ldg(&pre_b2[k]);
        bA = fmaf(p2, __ldg(&msg_W1[k * H + c]), bA);
        bB = fmaf(p2, __ldg(&msg_W1[H * H + k * H + c]), bB);
        bh = fmaf(7.f * __ldg(&msg_b2[k]), __ldg(&post_W1[k * H + c]), bh);
        bh = fmaf(p2, __ldg(&post_W1[H * H + k * H + c]), bh);
        bO = fmaf(8.f * __ldg(&post_b2[k]), __ldg(&out_W1[k * H + c]), bO);
    }
    g_bias[c]         = bA;
    g_bias[H + c]     = bB;
    g_bias[2 * H + c] = bh + __ldg(&post_b1[c]);
    g_bias[3 * H + c] = bO + __ldg(&out_b1[c]);
}

// ---- prep 3: pack 4 fused matrices into mma-B-fragment order ----
__global__ void prep_pack_kernel()
{
    int idx = blockIdx.x * blockDim.x + threadIdx.x;
    if (idx >= NMAT * MAT_ENTRIES) return;
    int t  = idx & 3;
    int c  = (idx >> 2) & 127;
    int kc = (idx >> 9) & 7;
    int m  = idx >> 12;

    const float* W = g_Wf + m * H * H;
    int k0 = kc * 16 + 2 * t;
    float w0 = W[(k0    ) * H + c];
    float w1 = W[(k0 + 1) * H + c];
    float w8 = W[(k0 + 8) * H + c];
    float w9 = W[(k0 + 9) * H + c];
    g_Wpk[idx] = pack_entry(w0, w1, w8, w9);
}

__device__ __forceinline__ void mma_bf16(float* c, const uint32_t* a, const uint32_t* b)
{
    asm volatile(
        "mma.sync.aligned.m16n8k16.row.col.f32.bf16.bf16.f32 "
        "{%0,%1,%2,%3}, {%4,%5,%6,%7}, {%8,%9}, {%0,%1,%2,%3};"
        : "+f"(c[0]), "+f"(c[1]), "+f"(c[2]), "+f"(c[3])
        : "r"(a[0]), "r"(a[1]), "r"(a[2]), "r"(a[3]), "r"(b[0]), "r"(b[1]));
}

// acc += X[32x128] @ W[128x128]; X fp32 in smem (stride AP), W packed bf16 hi/lo in g_Wpk.
// 4 warps: warp w covers cols w*32..w*32+31, rows 0..31. 3xBF16 compensated (hh+lh+hl).
__device__ __forceinline__ void gemm_acc(const float* __restrict__ X,
                                         int mat, float acc[2][4][4])
{
    const uint4* __restrict__ Wp = g_Wpk + mat * MAT_ENTRIES;
    const int lane = threadIdx.x & 31;
    const int warp = threadIdx.x >> 5;
    const int n0 = warp * 32;
    const int g = lane >> 2, tig = lane & 3;

#pragma unroll
    for (int kc = 0; kc < 8; ++kc) {
        const int kk = kc * 16;
        uint4 bfr[4];
#pragma unroll
        for (int nt = 0; nt < 4; ++nt)
            bfr[nt] = __ldg(&Wp[((kc << 7) + n0 + nt * 8 + g) * 4 + tig]);

        uint32_t ah[2][4], al[2][4];
#pragma unroll
        for (int mt = 0; mt < 2; ++mt) {
            int r = mt * 16 + g;
            float2 a01 = *(const float2*)&X[ r      * AP + kk + 2 * tig];
            float2 c01 = *(const float2*)&X[(r + 8) * AP + kk + 2 * tig];
            float2 a89 = *(const float2*)&X[ r      * AP + kk + 2 * tig + 8];
            float2 c89 = *(const float2*)&X[(r + 8) * AP + kk + 2 * tig + 8];
            bsplit2(a01, ah[mt][0], al[mt][0]);
            bsplit2(c01, ah[mt][1], al[mt][1]);
            bsplit2(a89, ah[mt][2], al[mt][2]);
            bsplit2(c89, ah[mt][3], al[mt][3]);
        }
#pragma unroll
        for (int mt = 0; mt < 2; ++mt)
#pragma unroll
            for (int nt = 0; nt < 4; ++nt) {
                uint32_t bh[2] = {bfr[nt].x, bfr[nt].y};
                uint32_t bl[2] = {bfr[nt].z, bfr[nt].w};
                mma_bf16(acc[mt][nt], ah[mt], bh);
                mma_bf16(acc[mt][nt], al[mt], bh);
                mma_bf16(acc[mt][nt], ah[mt], bl);
            }
    }
}

// fp32 epilogue: float2 stores into stride-AP buffer
__device__ __forceinline__ void gemm_epi(float acc[2][4][4], float* __restrict__ C,
                                         const float* __restrict__ gbias, bool doRelu)
{
    const int lane = threadIdx.x & 31;
    const int warp = threadIdx.x >> 5;
    const int n0 = warp * 32;
    const int g = lane >> 2, tig = lane & 3;
#pragma unroll
    for (int nt = 0; nt < 4; ++nt) {
        int c = n0 + nt * 8 + 2 * tig;
        float2 bz = make_float2(0.f, 0.f);
        if (gbias) bz = *(const float2*)&gbias[c];
#pragma unroll
        for (int mt = 0; mt < 2; ++mt) {
            int r = mt * 16 + g;
#pragma unroll
            for (int h = 0; h < 2; ++h) {
                int rr = r + h * 8;
                float vx = acc[mt][nt][h * 2 + 0] + bz.x;
                float vy = acc[mt][nt][h * 2 + 1] + bz.y;
                if (doRelu) { vx = fmaxf(vx, 0.f); vy = fmaxf(vy, 0.f); }
                *(float2*)&C[rr * AP + c] = make_float2(vx, vy);
            }
        }
    }
}

#define ACC_ZERO(acc) do {                                             \
    _Pragma("unroll")                                                  \
    for (int _m = 0; _m < 2; ++_m)                                     \
        _Pragma("unroll")                                              \
        for (int _n = 0; _n < 4; ++_n)                                 \
            _Pragma("unroll")                                          \
            for (int _i = 0; _i < 4; ++_i) acc[_m][_n][_i] = 0.f;      \
} while (0)

__global__ __launch_bounds__(NT, 4) void prettyrnn_kernel(
    const int* __restrict__ anchors, const int* __restrict__ n_jumps,
    const float* __restrict__ positions, const int* __restrict__ colors,
    const int* __restrict__ markers,
    const float* __restrict__ pre_W1, const float* __restrict__ pre_b1,
    const float* __restrict__ msg_W1, const float* __restrict__ msg_b1,
    const float* __restrict__ out_W2, const float* __restrict__ out_b2,
    float* __restrict__ out)
{
    extern __shared__ float sm[];
    float* sH  = sm + OFF_H;
    float* sA  = sm + OFF_A;
    float* sB  = sm + OFF_B;
    float* sG  = sm + OFF_G;
    float* sPos = sm + OFF_POS;
    float* sD  = sm + OFF_D;
    int* sCol = (int*)(sm + OFF_INT);
    int* sMrk = sCol + NODES;
    int* sAnc = sMrk + NODES;
    int* sJmp = sAnc + GPC;

    const int tid = threadIdx.x;
    const int lane = tid & 31;
    const int warp = tid >> 5;
    const int nodeBase = blockIdx.x * NODES;
    const int graphBase = blockIdx.x * GPC;
    const int tx = tid & 15;
    const int ty = tid >> 4;
    const int r0 = ty * 4;

    // ---- phase 0: per-node / per-graph inputs ----
    if (tid < NODES) {
        sCol[tid] = colors[nodeBase + tid];
        sMrk[tid] = markers[nodeBase + tid];
        sPos[2 * tid]     = positions[2 * (nodeBase + tid)];
        sPos[2 * tid + 1] = positions[2 * (nodeBase + tid) + 1];
    }
    if (tid >= NODES && tid < NODES + GPC) {
        int g = tid - NODES;
        sAnc[g] = anchors[graphBase + g];
        sJmp[g] = n_jumps[graphBase + g];
    }
    __syncthreads();

    // ---- distances ----
    for (int idx = tid; idx < NODES * 8; idx += NT) {
        int n = idx >> 3, jj = idx & 7;
        int j = (n & ~7) + jj;
        float dx = sPos[2 * n]     - sPos[2 * j];
        float dy = sPos[2 * n + 1] - sPos[2 * j + 1];
        sD[idx] = sqrtf(dx * dx + dy * dy);
    }

    // ---- pre layer 1 (coalesced gather): warp w -> rows 8w..8w+7, lane -> 4 consecutive cols ----
    {
        const float4* b1v = (const float4*)pre_b1;
#pragma unroll
        for (int r = 0; r < 8; ++r) {
            int n = warp * 8 + r;
            int g = n >> 3;
            float px = sPos[2 * n], py = sPos[2 * n + 1];
            const float4* rw0 = (const float4*)(pre_W1);
            const float4* rw1 = (const float4*)(pre_W1 + H);
            const float4* rc  = (const float4*)(pre_W1 + (2 + sCol[n]) * H);
            const float4* rm  = (const float4*)(pre_W1 + (10 + (sMrk[n] - 8)) * H);
            const float4* ra  = (const float4*)(pre_W1 + (18 + sAnc[g]) * H);
            const float4* rj  = (const float4*)(pre_W1 + (34 + sJmp[g]) * H);

            float4 vc = __ldg(&rc[lane]);
            float4 vm = __ldg(&rm[lane]);
            float4 va = __ldg(&ra[lane]);
            float4 vj = __ldg(&rj[lane]);
            float4 vb = __ldg(&b1v[lane]);
            float4 v0 = __ldg(&rw0[lane]);
            float4 v1 = __ldg(&rw1[lane]);

            float4 o;
            o.x = fmaxf(fmaf(px, v0.x, fmaf(py, v1.x, vc.x + vm.x + va.x + vj.x + vb.x)), 0.f);
            o.y = fmaxf(fmaf(px, v0.y, fmaf(py, v1.y, vc.y + vm.y + va.y + vj.y + vb.y)), 0.f);
            o.z = fmaxf(fmaf(px, v0.z, fmaf(py, v1.z, vc.z + vm.z + va.z + vj.z + vb.z)), 0.f);
            o.w = fmaxf(fmaf(px, v0.w, fmaf(py, v1.w, vc.w + vm.w + va.w + vj.w + vb.w)), 0.f);
            *(float4*)&sH[n * AP + 4 * lane] = o;
        }
    }
    __syncthreads();

    // ---- A = h1 @ W_A + bA -> sA ; B = h1 @ W_B + bB -> sB  (x0 fused away) ----
    {
        float acc[2][4][4]; ACC_ZERO(acc);
        gemm_acc(sH, 0, acc);
        gemm_epi(acc, sA, g_bias, false);
    }
    {
        float acc[2][4][4]; ACC_ZERO(acc);
        gemm_acc(sH, 1, acc);
        gemm_epi(acc, sB, g_bias + H, false);
    }
    __syncthreads();

    // ---- edge aggregation (register-blocked, conflict-free strips):
    //      thread owns cols {tx*4..+3, tx*4+64..+67} of its 4 rows.
    //      s[n] = sum_{j!=n} relu(A[n]+B[j]+d*w1d+b1) -> sA
    {
        const float* w1d = msg_W1 + 2 * H * H;
        const int octet = r0 & ~7;
#pragma unroll
        for (int half = 0; half < 2; ++half) {
            const int cb = tx * 4 + half * 64;
            float4 wv = __ldg((const float4*)&w1d[cb]);
            float4 bv = __ldg((const float4*)&msg_b1[cb]);
            float4 Brow[8];
#pragma unroll
            for (int j = 0; j < 8; ++j)
                Brow[j] = *(const float4*)&sB[(octet + j) * AP + cb];
#pragma unroll
            for (int i = 0; i < 4; ++i) {
                int n = r0 + i, nloc = n & 7;
                float4 a = *(const float4*)&sA[n * AP + cb];
                float4 s = make_float4(0.f, 0.f, 0.f, 0.f);
#pragma unroll
                for (int jj = 0; jj < 8; ++jj) {
                    if (jj == nloc) continue;
                    float d = sD[n * 8 + jj];
                    s.x += fmaxf(a.x + Brow[jj].x + fmaf(d, wv.x, bv.x), 0.f);
                    s.y += fmaxf(a.y + Brow[jj].y + fmaf(d, wv.y, bv.y), 0.f);
                    s.z += fmaxf(a.z + Brow[jj].z + fmaf(d, wv.z, bv.z), 0.f);
                    s.w += fmaxf(a.w + Brow[jj].w + fmaf(d, wv.w, bv.w), 0.f);
                }
                *(float4*)&sA[n * AP + cb] = s;
            }
        }
    }
    __syncthreads();

    // ---- post layer 1 (fused, upd eliminated): h = relu(s@W_SP + h1@W_XP + bh) -> sB ----
    {
        float acc[2][4][4]; ACC_ZERO(acc);
        gemm_acc(sA, 2, acc);
        gemm_acc(sH, 3, acc);
        gemm_epi(acc, sB, g_bias + 2 * H, true);
    }
    __syncthreads();

    // ---- graph sum of h -> sG  (post2 folded into W_PO) ----
    for (int idx = tid; idx < GPC * H; idx += NT) {
        int g = idx >> 7, k = idx & (H - 1);
        float s = 0.f;
#pragma unroll
        for (int i = 0; i < 8; ++i) s += sB[(g * 8 + i) * AP + k];
        sG[g * AP + k] = s;
    }
    __syncthreads();

    // ---- out layer 1 (SIMT, fused W_PO = post_W2@out_W1): ho = relu(gh @ W_PO + bO) -> sA ----
    {
        const float* WPO = g_Wf + 4 * H * H;
        float s0 = __ldg(&g_bias[3 * H + tid]);
        float s1 = s0, s2 = s0, s3 = s0;
#pragma unroll 4
        for (int kk = 0; kk < H; ++kk) {
            float w = __ldg(&WPO[kk * H + tid]);
            s0 = fmaf(sG[0 * AP + kk], w, s0);
            s1 = fmaf(sG[1 * AP + kk], w, s1);
            s2 = fmaf(sG[2 * AP + kk], w, s2);
            s3 = fmaf(sG[3 * AP + kk], w, s3);
        }
        sA[0 * AP + tid] = fmaxf(s0, 0.f);
        sA[1 * AP + tid] = fmaxf(s1, 0.f);
        sA[2 * AP + tid] = fmaxf(s2, 0.f);
        sA[3 * AP + tid] = fmaxf(s3, 0.f);
    }
    __syncthreads();

    // ---- out layer 2 (SIMT): logits -> gmem ----
    if (tid < GPC * 16) {
        int g = tid >> 4, o = tid & 15;
        float s = __ldg(&out_b2[o]);
#pragma unroll 8
        for (int k = 0; k < H; ++k)
            s = fmaf(sA[g * AP + k], __ldg(&out_W2[k * 16 + o]), s);
        out[(graphBase + g) * 16 + o] = s;
    }
}

extern "C" void kernel_launch(void* const* d_in, const int* in_sizes, int n_in,
                              void* d_out, int out_size)
{
    const int*   anchors   = (const int*)d_in[0];
    const int*   n_jumps   = (const int*)d_in[1];
    const float* positions = (const float*)d_in[2];
    const int*   colors    = (const int*)d_in[3];
    const int*   markers   = (const int*)d_in[4];
    const float* pre_W1  = (const float*)d_in[5];
    const float* pre_b1  = (const float*)d_in[6];
    const float* pre_W2  = (const float*)d_in[7];
    const float* pre_b2  = (const float*)d_in[8];
    const float* msg_W1  = (const float*)d_in[9];
    const float* msg_b1  = (const float*)d_in[10];
    const float* msg_W2  = (const float*)d_in[11];
    const float* msg_b2  = (const float*)d_in[12];
    const float* post_W1 = (const float*)d_in[13];
    const float* post_b1 = (const float*)d_in[14];
    const float* post_W2 = (const float*)d_in[15];
    const float* post_b2 = (const float*)d_in[16];
    const float* out_W1  = (const float*)d_in[17];
    const float* out_b1  = (const float*)d_in[18];
    const float* out_W2  = (const float*)d_in[19];
    const float* out_b2  = (const float*)d_in[20];

    // prep chain (deterministic, graph-capturable; sequential on stream)
    prep_fuse_kernel<<<(5 * H * H + 255) / 256, 256>>>(
        pre_W2, msg_W1, msg_W2, post_W1, post_W2, out_W1);
    prep_bias_kernel<<<1, H>>>(pre_b2, msg_W1, msg_b2, post_W1, post_b1,
                               post_b2, out_W1, out_b1);
    prep_pack_kernel<<<(NMAT * MAT_ENTRIES + 255) / 256, 256>>>();

    // main fused kernel
    int bs = in_sizes[0];
    int blocks = bs / GPC;
    size_t smemBytes = SMEM_FLOATS * sizeof(float);
    cudaFuncSetAttribute(prettyrnn_kernel,
                         cudaFuncAttributeMaxDynamicSharedMemorySize, (int)smemBytes);
    prettyrnn_kernel<<<blocks, NT, smemBytes>>>(
        anchors, n_jumps, positions, colors, markers,
        pre_W1, pre_b1,
        msg_W1, msg_b1,
        out_W2, out_b2,
        (float*)d_out);
}

// round 17
// speedup vs baseline: 1.3096x; 1.0110x over previous
#include <cuda_runtime.h>
#include <cuda_bf16.h>
#include <cstdint>
#include <math.h>

#define H 128
#define AP 136           // fp32 activation stride; 136 % 32 == 8 -> conflict-free LDS.64
#define NODES 32         // nodes per CTA
#define GPC 4            // graphs per CTA
#define NT 128

// shared layout (float offsets)
#define OFF_H   0                        // fp32 h1 (alive across whole kernel)
#define OFF_A   (OFF_H + NODES*AP)       // 4352: fp32 A / s
#define OFF_B   (OFF_A + NODES*AP)       // 8704: fp32 B / h
#define OFF_G   (OFF_B + NODES*AP)       // 13056: fp32 graph sums of h
#define OFF_POS (OFF_G + GPC*AP)         // 13600
#define OFF_D   (OFF_POS + NODES*2)      // 13664
#define OFF_INT (OFF_D + NODES*8)        // 13920
#define SMEM_FLOATS (OFF_INT + 80)       // 14000 floats = 56000 B -> 4 CTAs/SM

// packed weights: 4 matrices x [kc(8)][c(128)][t(4)] entries of uint4 {bh01, bh89, bl01, bl89}
// 0: W_A = pre_W2 @ M1a      1: W_B = pre_W2 @ M1b
// 2: W_SP = msg_W2 @ P1a     3: W_XP = pre_W2 @ P1b
#define NMAT 4
#define MAT_ENTRIES (8 * 128 * 4)
__device__ uint4 g_Wpk[NMAT * MAT_ENTRIES];        // 256 KB
__device__ float g_Wf[5 * H * H];                  // fp32 fused matrices; [4] = W_PO = post_W2@out_W1
__device__ __align__(16) float g_bias[4 * H];      // bA, bB, bh, bO

// ---- bf16 helpers ----
__device__ __forceinline__ uint32_t bpack(float lo, float hi) {   // lo -> bits[0:16), hi -> bits[16:32)
    uint32_t r;
    asm("cvt.rn.bf16x2.f32 %0, %1, %2;" : "=r"(r) : "f"(hi), "f"(lo));
    return r;
}
__device__ __forceinline__ float bf_lo(uint32_t p) { return __uint_as_float(p << 16); }
__device__ __forceinline__ float bf_hi(uint32_t p) { return __uint_as_float(p & 0xffff0000u); }

__device__ __forceinline__ void bsplit2(float2 v, uint32_t& h, uint32_t& l) {
    h = bpack(v.x, v.y);
    l = bpack(v.x - bf_lo(h), v.y - bf_hi(h));
}
__device__ __forceinline__ uint4 pack_entry(float v0, float v1, float v8, float v9) {
    uint32_t h01 = bpack(v0, v1);
    uint32_t l01 = bpack(v0 - bf_lo(h01), v1 - bf_hi(h01));
    uint32_t h89 = bpack(v8, v9);
    uint32_t l89 = bpack(v8 - bf_lo(h89), v9 - bf_hi(h89));
    return make_uint4(h01, h89, l01, l89);
}

// ---- prep 1: fused fp32 weight products ----
// g_Wf[m] = L @ R   (all [128,128] row-major: out[k][c] = sum_j L[k][j]*R[j][c])
__global__ void prep_fuse_kernel(const float* __restrict__ pre_W2,
                                 const float* __restrict__ msg_W1,
                                 const float* __restrict__ msg_W2,
                                 const float* __restrict__ post_W1,
                                 const float* __restrict__ post_W2,
                                 const float* __restrict__ out_W1)
{
    int idx = blockIdx.x * blockDim.x + threadIdx.x;
    if (idx >= 5 * H * H) return;
    int m = idx >> 14;
    int k = (idx >> 7) & 127;
    int c = idx & 127;
    const float* L;
    const float* R;
    switch (m) {
        case 0: L = pre_W2;  R = msg_W1; break;              // W_A
        case 1: L = pre_W2;  R = msg_W1 + H * H; break;      // W_B
        case 2: L = msg_W2;  R = post_W1; break;             // W_SP
        case 3: L = pre_W2;  R = post_W1 + H * H; break;     // W_XP
        default: L = post_W2; R = out_W1; break;             // W_PO
    }
    float s = 0.f;
#pragma unroll 8
    for (int j = 0; j < H; ++j)
        s = fmaf(__ldg(&L[k * H + j]), __ldg(&R[j * H + c]), s);
    g_Wf[idx] = s;
}

// ---- prep 2: fused bias vectors ----
// bA = pre_b2@M1a ; bB = pre_b2@M1b ; bh = 7*msg_b2@P1a + pre_b2@P1b + post_b1
// bO = 8*post_b2@out_W1 + out_b1
__global__ void prep_bias_kernel(const float* __restrict__ pre_b2,
                                 const float* __restrict__ msg_W1,
                                 const float* __restrict__ msg_b2,
                                 const float* __restrict__ post_W1,
                                 const float* __restrict__ post_b1,
                                 const float* __restrict__ post_b2,
                                 const float* __restrict__ out_W1,
                                 const float* __restrict__ out_b1)
{
    int c = threadIdx.x;
    if (c >= H) return;
    float bA = 0.f, bB = 0.f, bh = 0.f, bO = 0.f;
#pragma unroll 4
    for (int k = 0; k < H; ++k) {
        float p2 = __ldg(&pre_b2[k]);
        bA = fmaf(p2, __ldg(&msg_W1[k * H + c]), bA);
        bB = fmaf(p2, __ldg(&msg_W1[H * H + k * H + c]), bB);
        bh = fmaf(7.f * __ldg(&msg_b2[k]), __ldg(&post_W1[k * H + c]), bh);
        bh = fmaf(p2, __ldg(&post_W1[H * H + k * H + c]), bh);
        bO = fmaf(8.f * __ldg(&post_b2[k]), __ldg(&out_W1[k * H + c]), bO);
    }
    g_bias[c]         = bA;
    g_bias[H + c]     = bB;
    g_bias[2 * H + c] = bh + __ldg(&post_b1[c]);
    g_bias[3 * H + c] = bO + __ldg(&out_b1[c]);
}

// ---- prep 3: pack 4 fused matrices into mma-B-fragment order ----
__global__ void prep_pack_kernel()
{
    int idx = blockIdx.x * blockDim.x + threadIdx.x;
    if (idx >= NMAT * MAT_ENTRIES) return;
    int t  = idx & 3;
    int c  = (idx >> 2) & 127;
    int kc = (idx >> 9) & 7;
    int m  = idx >> 12;

    const float* W = g_Wf + m * H * H;
    int k0 = kc * 16 + 2 * t;
    float w0 = W[(k0    ) * H + c];
    float w1 = W[(k0 + 1) * H + c];
    float w8 = W[(k0 + 8) * H + c];
    float w9 = W[(k0 + 9) * H + c];
    g_Wpk[idx] = pack_entry(w0, w1, w8, w9);
}

__device__ __forceinline__ void mma_bf16(float* c, const uint32_t* a, const uint32_t* b)
{
    asm volatile(
        "mma.sync.aligned.m16n8k16.row.col.f32.bf16.bf16.f32 "
        "{%0,%1,%2,%3}, {%4,%5,%6,%7}, {%8,%9}, {%0,%1,%2,%3};"
        : "+f"(c[0]), "+f"(c[1]), "+f"(c[2]), "+f"(c[3])
        : "r"(a[0]), "r"(a[1]), "r"(a[2]), "r"(a[3]), "r"(b[0]), "r"(b[1]));
}

// acc += X[32x128] @ W[128x128]; X fp32 in smem (stride AP), W packed bf16 hi/lo in g_Wpk.
// 4 warps: warp w covers cols w*32..w*32+31, rows 0..31. 3xBF16 compensated (hh+lh+hl).
__device__ __forceinline__ void gemm_acc(const float* __restrict__ X,
                                         int mat, float acc[2][4][4])
{
    const uint4* __restrict__ Wp = g_Wpk + mat * MAT_ENTRIES;
    const int lane = threadIdx.x & 31;
    const int warp = threadIdx.x >> 5;
    const int n0 = warp * 32;
    const int g = lane >> 2, tig = lane & 3;

#pragma unroll
    for (int kc = 0; kc < 8; ++kc) {
        const int kk = kc * 16;
        uint4 bfr[4];
#pragma unroll
        for (int nt = 0; nt < 4; ++nt)
            bfr[nt] = __ldg(&Wp[((kc << 7) + n0 + nt * 8 + g) * 4 + tig]);

        uint32_t ah[2][4], al[2][4];
#pragma unroll
        for (int mt = 0; mt < 2; ++mt) {
            int r = mt * 16 + g;
            float2 a01 = *(const float2*)&X[ r      * AP + kk + 2 * tig];
            float2 c01 = *(const float2*)&X[(r + 8) * AP + kk + 2 * tig];
            float2 a89 = *(const float2*)&X[ r      * AP + kk + 2 * tig + 8];
            float2 c89 = *(const float2*)&X[(r + 8) * AP + kk + 2 * tig + 8];
            bsplit2(a01, ah[mt][0], al[mt][0]);
            bsplit2(c01, ah[mt][1], al[mt][1]);
            bsplit2(a89, ah[mt][2], al[mt][2]);
            bsplit2(c89, ah[mt][3], al[mt][3]);
        }
#pragma unroll
        for (int mt = 0; mt < 2; ++mt)
#pragma unroll
            for (int nt = 0; nt < 4; ++nt) {
                uint32_t bh[2] = {bfr[nt].x, bfr[nt].y};
                uint32_t bl[2] = {bfr[nt].z, bfr[nt].w};
                mma_bf16(acc[mt][nt], ah[mt], bh);
                mma_bf16(acc[mt][nt], al[mt], bh);
                mma_bf16(acc[mt][nt], ah[mt], bl);
            }
    }
}

// dual-matrix variant: one pass over X, A-frags loaded/split ONCE, MMAs for both matrices.
__device__ __forceinline__ void gemm_acc2(const float* __restrict__ X,
                                          int matA, int matB,
                                          float accA[2][4][4], float accB[2][4][4])
{
    const uint4* __restrict__ WpA = g_Wpk + matA * MAT_ENTRIES;
    const uint4* __restrict__ WpB = g_Wpk + matB * MAT_ENTRIES;
    const int lane = threadIdx.x & 31;
    const int warp = threadIdx.x >> 5;
    const int n0 = warp * 32;
    const int g = lane >> 2, tig = lane & 3;

#pragma unroll
    for (int kc = 0; kc < 8; ++kc) {
        const int kk = kc * 16;
        const int widx = ((kc << 7) + n0 + g) * 4 + tig;

        uint32_t ah[2][4], al[2][4];
#pragma unroll
        for (int mt = 0; mt < 2; ++mt) {
            int r = mt * 16 + g;
            float2 a01 = *(const float2*)&X[ r      * AP + kk + 2 * tig];
            float2 c01 = *(const float2*)&X[(r + 8) * AP + kk + 2 * tig];
            float2 a89 = *(const float2*)&X[ r      * AP + kk + 2 * tig + 8];
            float2 c89 = *(const float2*)&X[(r + 8) * AP + kk + 2 * tig + 8];
            bsplit2(a01, ah[mt][0], al[mt][0]);
            bsplit2(c01, ah[mt][1], al[mt][1]);
            bsplit2(a89, ah[mt][2], al[mt][2]);
            bsplit2(c89, ah[mt][3], al[mt][3]);
        }
        // matrix A MMAs
        {
            uint4 bfr[4];
#pragma unroll
            for (int nt = 0; nt < 4; ++nt)
                bfr[nt] = __ldg(&WpA[widx + nt * 32]);
#pragma unroll
            for (int mt = 0; mt < 2; ++mt)
#pragma unroll
                for (int nt = 0; nt < 4; ++nt) {
                    uint32_t bh[2] = {bfr[nt].x, bfr[nt].y};
                    uint32_t bl[2] = {bfr[nt].z, bfr[nt].w};
                    mma_bf16(accA[mt][nt], ah[mt], bh);
                    mma_bf16(accA[mt][nt], al[mt], bh);
                    mma_bf16(accA[mt][nt], ah[mt], bl);
                }
        }
        // matrix B MMAs
        {
            uint4 bfr[4];
#pragma unroll
            for (int nt = 0; nt < 4; ++nt)
                bfr[nt] = __ldg(&WpB[widx + nt * 32]);
#pragma unroll
            for (int mt = 0; mt < 2; ++mt)
#pragma unroll
                for (int nt = 0; nt < 4; ++nt) {
                    uint32_t bh[2] = {bfr[nt].x, bfr[nt].y};
                    uint32_t bl[2] = {bfr[nt].z, bfr[nt].w};
                    mma_bf16(accB[mt][nt], ah[mt], bh);
                    mma_bf16(accB[mt][nt], al[mt], bh);
                    mma_bf16(accB[mt][nt], ah[mt], bl);
                }
        }
    }
}

// fp32 epilogue: float2 stores into stride-AP buffer
__device__ __forceinline__ void gemm_epi(float acc[2][4][4], float* __restrict__ C,
                                         const float* __restrict__ gbias, bool doRelu)
{
    const int lane = threadIdx.x & 31;
    const int warp = threadIdx.x >> 5;
    const int n0 = warp * 32;
    const int g = lane >> 2, tig = lane & 3;
#pragma unroll
    for (int nt = 0; nt < 4; ++nt) {
        int c = n0 + nt * 8 + 2 * tig;
        float2 bz = make_float2(0.f, 0.f);
        if (gbias) bz = *(const float2*)&gbias[c];
#pragma unroll
        for (int mt = 0; mt < 2; ++mt) {
            int r = mt * 16 + g;
#pragma unroll
            for (int h = 0; h < 2; ++h) {
                int rr = r + h * 8;
                float vx = acc[mt][nt][h * 2 + 0] + bz.x;
                float vy = acc[mt][nt][h * 2 + 1] + bz.y;
                if (doRelu) { vx = fmaxf(vx, 0.f); vy = fmaxf(vy, 0.f); }
                *(float2*)&C[rr * AP + c] = make_float2(vx, vy);
            }
        }
    }
}

#define ACC_ZERO(acc) do {                                             \
    _Pragma("unroll")                                                  \
    for (int _m = 0; _m < 2; ++_m)                                     \
        _Pragma("unroll")                                              \
        for (int _n = 0; _n < 4; ++_n)                                 \
            _Pragma("unroll")                                          \
            for (int _i = 0; _i < 4; ++_i) acc[_m][_n][_i] = 0.f;      \
} while (0)

__global__ __launch_bounds__(NT, 4) void prettyrnn_kernel(
    const int* __restrict__ anchors, const int* __restrict__ n_jumps,
    const float* __restrict__ positions, const int* __restrict__ colors,
    const int* __restrict__ markers,
    const float* __restrict__ pre_W1, const float* __restrict__ pre_b1,
    const float* __restrict__ msg_W1, const float* __restrict__ msg_b1,
    const float* __restrict__ out_W2, const float* __restrict__ out_b2,
    float* __restrict__ out)
{
    extern __shared__ float sm[];
    float* sH  = sm + OFF_H;
    float* sA  = sm + OFF_A;
    float* sB  = sm + OFF_B;
    float* sG  = sm + OFF_G;
    float* sPos = sm + OFF_POS;
    float* sD  = sm + OFF_D;
    int* sCol = (int*)(sm + OFF_INT);
    int* sMrk = sCol + NODES;
    int* sAnc = sMrk + NODES;
    int* sJmp = sAnc + GPC;

    const int tid = threadIdx.x;
    const int lane = tid & 31;
    const int warp = tid >> 5;
    const int nodeBase = blockIdx.x * NODES;
    const int graphBase = blockIdx.x * GPC;
    const int tx = tid & 15;
    const int ty = tid >> 4;
    const int r0 = ty * 4;

    // ---- phase 0: per-node / per-graph inputs ----
    if (tid < NODES) {
        sCol[tid] = colors[nodeBase + tid];
        sMrk[tid] = markers[nodeBase + tid];
        sPos[2 * tid]     = positions[2 * (nodeBase + tid)];
        sPos[2 * tid + 1] = positions[2 * (nodeBase + tid) + 1];
    }
    if (tid >= NODES && tid < NODES + GPC) {
        int g = tid - NODES;
        sAnc[g] = anchors[graphBase + g];
        sJmp[g] = n_jumps[graphBase + g];
    }
    __syncthreads();

    // ---- distances ----
    for (int idx = tid; idx < NODES * 8; idx += NT) {
        int n = idx >> 3, jj = idx & 7;
        int j = (n & ~7) + jj;
        float dx = sPos[2 * n]     - sPos[2 * j];
        float dy = sPos[2 * n + 1] - sPos[2 * j + 1];
        sD[idx] = sqrtf(dx * dx + dy * dy);
    }

    // ---- pre layer 1 (coalesced gather): warp w -> rows 8w..8w+7, lane -> 4 consecutive cols ----
    {
        const float4* b1v = (const float4*)pre_b1;
#pragma unroll
        for (int r = 0; r < 8; ++r) {
            int n = warp * 8 + r;
            int g = n >> 3;
            float px = sPos[2 * n], py = sPos[2 * n + 1];
            const float4* rw0 = (const float4*)(pre_W1);
            const float4* rw1 = (const float4*)(pre_W1 + H);
            const float4* rc  = (const float4*)(pre_W1 + (2 + sCol[n]) * H);
            const float4* rm  = (const float4*)(pre_W1 + (10 + (sMrk[n] - 8)) * H);
            const float4* ra  = (const float4*)(pre_W1 + (18 + sAnc[g]) * H);
            const float4* rj  = (const float4*)(pre_W1 + (34 + sJmp[g]) * H);

            float4 vc = __ldg(&rc[lane]);
            float4 vm = __ldg(&rm[lane]);
            float4 va = __ldg(&ra[lane]);
            float4 vj = __ldg(&rj[lane]);
            float4 vb = __ldg(&b1v[lane]);
            float4 v0 = __ldg(&rw0[lane]);
            float4 v1 = __ldg(&rw1[lane]);

            float4 o;
            o.x = fmaxf(fmaf(px, v0.x, fmaf(py, v1.x, vc.x + vm.x + va.x + vj.x + vb.x)), 0.f);
            o.y = fmaxf(fmaf(px, v0.y, fmaf(py, v1.y, vc.y + vm.y + va.y + vj.y + vb.y)), 0.f);
            o.z = fmaxf(fmaf(px, v0.z, fmaf(py, v1.z, vc.z + vm.z + va.z + vj.z + vb.z)), 0.f);
            o.w = fmaxf(fmaf(px, v0.w, fmaf(py, v1.w, vc.w + vm.w + va.w + vj.w + vb.w)), 0.f);
            *(float4*)&sH[n * AP + 4 * lane] = o;
        }
    }
    __syncthreads();

    // ---- A = h1 @ W_A + bA -> sA ; B = h1 @ W_B + bB -> sB  (single pass, shared A-frags) ----
    {
        float accA[2][4][4], accB[2][4][4];
        ACC_ZERO(accA); ACC_ZERO(accB);
        gemm_acc2(sH, 0, 1, accA, accB);
        gemm_epi(accA, sA, g_bias, false);
        gemm_epi(accB, sB, g_bias + H, false);
    }
    __syncthreads();

    // ---- edge aggregation (register-blocked, conflict-free strips):
    //      thread owns cols {tx*4..+3, tx*4+64..+67} of its 4 rows.
    //      s[n] = sum_{j!=n} relu(A[n]+B[j]+d*w1d+b1) -> sA
    {
        const float* w1d = msg_W1 + 2 * H * H;
        const int octet = r0 & ~7;
#pragma unroll
        for (int half = 0; half < 2; ++half) {
            const int cb = tx * 4 + half * 64;
            float4 wv = __ldg((const float4*)&w1d[cb]);
            float4 bv = __ldg((const float4*)&msg_b1[cb]);
            float4 Brow[8];
#pragma unroll
            for (int j = 0; j < 8; ++j)
                Brow[j] = *(const float4*)&sB[(octet + j) * AP + cb];
#pragma unroll
            for (int i = 0; i < 4; ++i) {
                int n = r0 + i, nloc = n & 7;
                float4 a = *(const float4*)&sA[n * AP + cb];
                float4 s = make_float4(0.f, 0.f, 0.f, 0.f);
#pragma unroll
                for (int jj = 0; jj < 8; ++jj) {
                    if (jj == nloc) continue;
                    float d = sD[n * 8 + jj];
                    s.x += fmaxf(a.x + Brow[jj].x + fmaf(d, wv.x, bv.x), 0.f);
                    s.y += fmaxf(a.y + Brow[jj].y + fmaf(d, wv.y, bv.y), 0.f);
                    s.z += fmaxf(a.z + Brow[jj].z + fmaf(d, wv.z, bv.z), 0.f);
                    s.w += fmaxf(a.w + Brow[jj].w + fmaf(d, wv.w, bv.w), 0.f);
                }
                *(float4*)&sA[n * AP + cb] = s;
            }
        }
    }
    __syncthreads();

    // ---- post layer 1 (fused, upd eliminated): h = relu(s@W_SP + h1@W_XP + bh) -> sB ----
    {
        float acc[2][4][4]; ACC_ZERO(acc);
        gemm_acc(sA, 2, acc);
        gemm_acc(sH, 3, acc);
        gemm_epi(acc, sB, g_bias + 2 * H, true);
    }
    __syncthreads();

    // ---- graph sum of h -> sG  (post2 folded into W_PO) ----
    for (int idx = tid; idx < GPC * H; idx += NT) {
        int g = idx >> 7, k = idx & (H - 1);
        float s = 0.f;
#pragma unroll
        for (int i = 0; i < 8; ++i) s += sB[(g * 8 + i) * AP + k];
        sG[g * AP + k] = s;
    }
    __syncthreads();

    // ---- out layer 1 (SIMT, fused W_PO = post_W2@out_W1): ho = relu(gh @ W_PO + bO) -> sA ----
    {
        const float* WPO = g_Wf + 4 * H * H;
        float s0 = __ldg(&g_bias[3 * H + tid]);
        float s1 = s0, s2 = s0, s3 = s0;
#pragma unroll 4
        for (int kk = 0; kk < H; ++kk) {
            float w = __ldg(&WPO[kk * H + tid]);
            s0 = fmaf(sG[0 * AP + kk], w, s0);
            s1 = fmaf(sG[1 * AP + kk], w, s1);
            s2 = fmaf(sG[2 * AP + kk], w, s2);
            s3 = fmaf(sG[3 * AP + kk], w, s3);
        }
        sA[0 * AP + tid] = fmaxf(s0, 0.f);
        sA[1 * AP + tid] = fmaxf(s1, 0.f);
        sA[2 * AP + tid] = fmaxf(s2, 0.f);
        sA[3 * AP + tid] = fmaxf(s3, 0.f);
    }
    __syncthreads();

    // ---- out layer 2 (SIMT): logits -> gmem ----
    if (tid < GPC * 16) {
        int g = tid >> 4, o = tid & 15;
        float s = __ldg(&out_b2[o]);
#pragma unroll 8
        for (int k = 0; k < H; ++k)
            s = fmaf(sA[g * AP + k], __ldg(&out_W2[k * 16 + o]), s);
        out[(graphBase + g) * 16 + o] = s;
    }
}

extern "C" void kernel_launch(void* const* d_in, const int* in_sizes, int n_in,
                              void* d_out, int out_size)
{
    const int*   anchors   = (const int*)d_in[0];
    const int*   n_jumps   = (const int*)d_in[1];
    const float* positions = (const float*)d_in[2];
    const int*   colors    = (const int*)d_in[3];
    const int*   markers   = (const int*)d_in[4];
    const float* pre_W1  = (const float*)d_in[5];
    const float* pre_b1  = (const float*)d_in[6];
    const float* pre_W2  = (const float*)d_in[7];
    const float* pre_b2  = (const float*)d_in[8];
    const float* msg_W1  = (const float*)d_in[9];
    const float* msg_b1  = (const float*)d_in[10];
    const float* msg_W2  = (const float*)d_in[11];
    const float* msg_b2  = (const float*)d_in[12];
    const float* post_W1 = (const float*)d_in[13];
    const float* post_b1 = (const float*)d_in[14];
    const float* post_W2 = (const float*)d_in[15];
    const float* post_b2 = (const float*)d_in[16];
    const float* out_W1  = (const float*)d_in[17];
    const float* out_b1  = (const float*)d_in[18];
    const float* out_W2  = (const float*)d_in[19];
    const float* out_b2  = (const float*)d_in[20];

    // prep chain (deterministic, graph-capturable; sequential on stream)
    prep_fuse_kernel<<<(5 * H * H + 255) / 256, 256>>>(
        pre_W2, msg_W1, msg_W2, post_W1, post_W2, out_W1);
    prep_bias_kernel<<<1, H>>>(pre_b2, msg_W1, msg_b2, post_W1, post_b1,
                               post_b2, out_W1, out_b1);
    prep_pack_kernel<<<(NMAT * MAT_ENTRIES + 255) / 256, 256>>>();

    // main fused kernel
    int bs = in_sizes[0];
    int blocks = bs / GPC;
    size_t smemBytes = SMEM_FLOATS * sizeof(float);
    cudaFuncSetAttribute(prettyrnn_kernel,
                         cudaFuncAttributeMaxDynamicSharedMemorySize, (int)smemBytes);
    prettyrnn_kernel<<<blocks, NT, smemBytes>>>(
        anchors, n_jumps, positions, colors, markers,
        pre_W1, pre_b1,
        msg_W1, msg_b1,
        out_W2, out_b2,
        (float*)d_out);
}